// round 2
// baseline (speedup 1.0000x reference)
#include <cuda_runtime.h>
#include <cstdint>

#define HDIM 1024
#define BSZ 64
#define TLEN 512
#define G4 4096
#define KC 32
#define LDS 36
#define NBLK 128

// scratch (device statics; no allocations)
__device__ float g_G0[268435456];          // [T][dir][B][4096] precomputed x-gates (+bias), 1 GiB
__device__ float g_bsum[4][G4];            // bias sums: f0, b0, f1, b1
__device__ float g_h0[2][BSZ * HDIM];      // layer0 carried h (backward), ping-pong
__device__ float g_c0[2][BSZ * HDIM];
__device__ float g_h1[2][BSZ * HDIM];      // layer1 carried h (backward), ping-pong
__device__ float g_c1[2][BSZ * HDIM];
__device__ float g_hf0[2][BSZ * HDIM];     // layer0 forward h, ping-pong (WAR safety)
__device__ unsigned g_gen;
__device__ unsigned g_cnt;

__device__ __forceinline__ float f2tf32(float x) {
    unsigned u;
    asm("cvt.rna.tf32.f32 %0, %1;" : "=r"(u) : "f"(x));
    return __uint_as_float(u);
}

__device__ __forceinline__ void mma8(float acc[4], const float a[4], const float b[2]) {
    const unsigned* A = reinterpret_cast<const unsigned*>(a);
    const unsigned* B = reinterpret_cast<const unsigned*>(b);
    asm volatile(
        "mma.sync.aligned.m16n8k8.row.col.f32.tf32.tf32.f32 "
        "{%0,%1,%2,%3}, {%4,%5,%6,%7}, {%8,%9}, {%0,%1,%2,%3};\n"
        : "+f"(acc[0]), "+f"(acc[1]), "+f"(acc[2]), "+f"(acc[3])
        : "r"(A[0]), "r"(A[1]), "r"(A[2]), "r"(A[3]), "r"(B[0]), "r"(B[1]));
}

__device__ __forceinline__ float sigf(float x) { return 1.0f / (1.0f + expf(-x)); }

__device__ __forceinline__ float4 cvt4(float4 v) {
    v.x = f2tf32(v.x); v.y = f2tf32(v.y); v.z = f2tf32(v.z); v.w = f2tf32(v.w);
    return v;
}

// Software grid barrier. Safe: 128 blocks <= 148 SMs, all co-resident.
// __threadfence() (gpu scope) emits CCTL.IVALL on sm_103a -> invalidates this
// SM's L1D, so post-barrier loads see other blocks' writes.
__device__ __forceinline__ void grid_bar() {
    __syncthreads();
    if (threadIdx.x == 0) {
        volatile unsigned* vg = &g_gen;
        unsigned gen = *vg;
        __threadfence();                       // release: my writes visible before arrive
        if (atomicAdd(&g_cnt, 1u) == NBLK - 1) {
            g_cnt = 0;
            __threadfence();
            *vg = gen + 1;
        } else {
            while (*vg == gen) { __nanosleep(40); }
        }
        __threadfence();                       // acquire: flush L1D before reloading state
    }
    __syncthreads();
}

// ---------------------------------------------------------------------------
// One GEMM+LSTM phase of the scan.
// mode 1: layer0  gates = G0[t] + h_prev0 @ Whh0^T           (K=1024)
// mode 2: layer1  gates = h_in @ Wih1^T + h_prev1 @ Whh1^T   (K=2048)
// Block computes M=64 (batch) x N=64 (4 gates x 16 units at n0).
// ---------------------------------------------------------------------------
__device__ __forceinline__ void scan_phase(
    int mode, int t, int dir, int n0,
    const float* __restrict__ Wih_f, const float* __restrict__ Whh_f,
    const float* __restrict__ Wih_b, const float* __restrict__ Whh_b,
    float* __restrict__ dout,
    float* sAb, float* sWb)
{
    const int tid = threadIdx.x;
    const int p = t & 1;

    const float *A0, *A1, *W0, *W1;
    int nkc;
    if (mode == 1) {
        A0 = A1 = g_h0[p];
        W0 = W1 = dir ? Whh_b : Whh_f;
        nkc = 32;
    } else {
        A0 = dir ? g_h0[1 - p] : g_hf0[1 - p];
        A1 = g_h1[p];
        W0 = (dir ? Wih_b : Wih_f) + (size_t)G4 * HDIM;
        W1 = (dir ? Whh_b : Whh_f) + (size_t)G4 * HDIM;
        nkc = 64;
    }

    const int rowA0 = tid >> 3, kq = tid & 7, rowA1 = rowA0 + 32;
    const int wr0 = ((rowA0 >> 4) << 10) + n0 + (rowA0 & 15);
    const int wr1 = ((rowA1 >> 4) << 10) + n0 + (rowA1 & 15);

    float4 ra0, ra1, rw0, rw1;

    auto do_load = [&](int kc) {
        int sel = kc >= 32;
        const float* Ap = sel ? A1 : A0;
        const float* Wp = sel ? W1 : W0;
        int kl = (kc & 31) * KC + kq * 4;
        ra0 = *(const float4*)(Ap + (size_t)rowA0 * HDIM + kl);
        ra1 = *(const float4*)(Ap + (size_t)rowA1 * HDIM + kl);
        rw0 = *(const float4*)(Wp + (size_t)wr0 * HDIM + kl);
        rw1 = *(const float4*)(Wp + (size_t)wr1 * HDIM + kl);
    };
    auto do_store = [&](int buf) {
        float* sA = sAb + buf * (64 * LDS);
        float* sW = sWb + buf * (64 * LDS);
        *(float4*)(sA + rowA0 * LDS + kq * 4) = cvt4(ra0);
        *(float4*)(sA + rowA1 * LDS + kq * 4) = cvt4(ra1);
        *(float4*)(sW + rowA0 * LDS + kq * 4) = cvt4(rw0);
        *(float4*)(sW + rowA1 * LDS + kq * 4) = cvt4(rw1);
    };

    const int wid = tid >> 5, lane = tid & 31;
    const int wm = wid & 3, wn = wid >> 2;      // warp tile: 16 rows x 32 cols
    const int gq = lane >> 2, tig = lane & 3;

    float acc[4][4];
    #pragma unroll
    for (int i = 0; i < 4; i++)
        #pragma unroll
        for (int j = 0; j < 4; j++) acc[i][j] = 0.f;

    do_load(0);
    do_store(0);
    __syncthreads();

    for (int kc = 0; kc < nkc; kc++) {
        int buf = kc & 1;
        if (kc + 1 < nkc) do_load(kc + 1);
        const float* sA = sAb + buf * (64 * LDS);
        const float* sW = sWb + buf * (64 * LDS);
        const float* aB = sA + (wm * 16 + gq) * LDS;
        #pragma unroll
        for (int k8 = 0; k8 < 4; k8++) {
            int kk = k8 * 8;
            float af[4];
            af[0] = aB[kk + tig];
            af[1] = aB[8 * LDS + kk + tig];
            af[2] = aB[kk + tig + 4];
            af[3] = aB[8 * LDS + kk + tig + 4];
            #pragma unroll
            for (int nt = 0; nt < 4; nt++) {
                int nl = wn * 32 + nt * 8 + gq;
                float bf[2];
                bf[0] = sW[nl * LDS + kk + tig];
                bf[1] = sW[nl * LDS + kk + tig + 4];
                mma8(acc[nt], af, bf);
            }
        }
        if (kc + 1 < nkc) do_store(buf ^ 1);
        __syncthreads();
    }

    // gather accumulators so each thread sees all 4 gates of one (batch, unit)
    float* gsm = sAb;   // reused as 64 x 65
    {
        int r0 = wm * 16 + gq;
        #pragma unroll
        for (int nt = 0; nt < 4; nt++) {
            int cc = wn * 32 + nt * 8 + tig * 2;
            gsm[r0 * 65 + cc] = acc[nt][0];
            gsm[r0 * 65 + cc + 1] = acc[nt][1];
            gsm[(r0 + 8) * 65 + cc] = acc[nt][2];
            gsm[(r0 + 8) * 65 + cc + 1] = acc[nt][3];
        }
    }
    __syncthreads();

    #pragma unroll
    for (int r = 0; r < 4; r++) {
        int idx = tid + 256 * r;
        int m = idx >> 4, j = idx & 15;
        float gi = gsm[m * 65 + j];
        float gf = gsm[m * 65 + 16 + j];
        float gg = gsm[m * 65 + 32 + j];
        float go = gsm[m * 65 + 48 + j];
        int n = n0 + j;
        int hi = m * HDIM + n;
        if (mode == 1) {
            const float* G0p = g_G0 + ((size_t)(t * 2 + dir) * 64 + m) * (size_t)G4;
            gi += G0p[n]; gf += G0p[HDIM + n]; gg += G0p[2 * HDIM + n]; go += G0p[3 * HDIM + n];
            float cp = g_c0[p][hi];
            float c2 = sigf(gf) * cp + sigf(gi) * tanhf(gg);
            float h2 = sigf(go) * tanhf(c2);
            if (dir == 0) {
                g_hf0[1 - p][hi] = h2;
            } else {
                g_h0[1 - p][hi] = h2;
                g_c0[1 - p][hi] = c2;
            }
        } else {
            gi += g_bsum[2 + dir][n];
            gf += g_bsum[2 + dir][HDIM + n];
            gg += g_bsum[2 + dir][2 * HDIM + n];
            go += g_bsum[2 + dir][3 * HDIM + n];
            float cp = g_c1[p][hi];
            float c2 = sigf(gf) * cp + sigf(gi) * tanhf(gg);
            float h2 = sigf(go) * tanhf(c2);
            size_t ob = ((size_t)m * TLEN + t) * 2048 + (size_t)dir * HDIM + n;
            dout[ob] = h2;                            // out
            dout[67108864 + ob] = c2;                 // c_out
            if (t == TLEN - 1) {
                size_t lb = (size_t)m * 2048 + (size_t)dir * HDIM + n;
                dout[134217728 + lb] = h2;            // out[:, -1]
                dout[134217728 + 131072 + lb] = c2;   // c_out[:, -1]
            }
            if (dir == 1) {
                g_h1[1 - p][hi] = h2;
                g_c1[1 - p][hi] = c2;
            }
        }
    }
    __syncthreads();   // protect gsm (sAb) before next phase's do_store(0)
}

// Persistent scan kernel: entire 512-step recurrence in ONE launch.
__global__ __launch_bounds__(256) void scan_kernel(
    const float* __restrict__ Wih_f, const float* __restrict__ Whh_f,
    const float* __restrict__ Wih_b, const float* __restrict__ Whh_b,
    float* __restrict__ dout)
{
    __shared__ float sA[2][64 * LDS];
    __shared__ float sW[2][64 * LDS];
    const int bx = blockIdx.x;
    const int dir = bx >> 6;
    const int n0 = (bx & 63) * 16;

    for (int t = 0; t < TLEN; t++) {
        scan_phase(1, t, dir, n0, Wih_f, Whh_f, Wih_b, Whh_b, dout, &sA[0][0], &sW[0][0]);
        grid_bar();
        scan_phase(2, t, dir, n0, Wih_f, Whh_f, Wih_b, Whh_b, dout, &sA[0][0], &sW[0][0]);
        // no barrier needed here: layer0(t+1) writes only parity-p buffers,
        // which in-flight layer1(t) never touches; the t+1 barrier fences all.
    }
}

// Precompute G0 = x @ Wih0^T (+ bias sums), both directions (feature-reversed
// A-loads for backward). M = B*T = 32768, N = 2 x 4096, K = 1024.
__global__ __launch_bounds__(256) void g0_kernel(
    const float* __restrict__ x,
    const float* __restrict__ Wih_f, const float* __restrict__ Wih_b)
{
    __shared__ float sA[2][64 * LDS];
    __shared__ float sW[2][64 * LDS];

    const int tid = threadIdx.x;
    const int bx = blockIdx.x;
    const int mtile = bx >> 7;
    const int ntile = bx & 127;
    const int dir = ntile >> 6;
    const bool revA = (dir == 1);
    const float* Ap = x + (size_t)mtile * 64 * HDIM;
    const float* Wp = dir ? Wih_b : Wih_f;
    const int wrowbase = (ntile & 63) * 64;

    const int rowA0 = tid >> 3, kq = tid & 7, rowA1 = rowA0 + 32;
    const int wr0 = wrowbase + rowA0;
    const int wr1 = wrowbase + rowA1;

    float4 ra0, ra1, rw0, rw1;
    auto do_load = [&](int kc) {
        int kl = kc * KC + kq * 4;
        if (!revA) {
            ra0 = *(const float4*)(Ap + (size_t)rowA0 * HDIM + kl);
            ra1 = *(const float4*)(Ap + (size_t)rowA1 * HDIM + kl);
        } else {
            ra0 = *(const float4*)(Ap + (size_t)rowA0 * HDIM + (HDIM - 4) - kl);
            ra1 = *(const float4*)(Ap + (size_t)rowA1 * HDIM + (HDIM - 4) - kl);
        }
        rw0 = *(const float4*)(Wp + (size_t)wr0 * HDIM + kl);
        rw1 = *(const float4*)(Wp + (size_t)wr1 * HDIM + kl);
    };
    auto rev4 = [](float4 v) { float4 r; r.x = v.w; r.y = v.z; r.z = v.y; r.w = v.x; return r; };
    auto do_store = [&](int buf) {
        float4 a0 = cvt4(ra0), a1 = cvt4(ra1);
        if (revA) { a0 = rev4(a0); a1 = rev4(a1); }
        *(float4*)(&sA[buf][rowA0 * LDS + kq * 4]) = a0;
        *(float4*)(&sA[buf][rowA1 * LDS + kq * 4]) = a1;
        *(float4*)(&sW[buf][rowA0 * LDS + kq * 4]) = cvt4(rw0);
        *(float4*)(&sW[buf][rowA1 * LDS + kq * 4]) = cvt4(rw1);
    };

    const int wid = tid >> 5, lane = tid & 31;
    const int wm = wid & 3, wn = wid >> 2;
    const int gq = lane >> 2, tig = lane & 3;

    float acc[4][4];
    #pragma unroll
    for (int i = 0; i < 4; i++)
        #pragma unroll
        for (int j = 0; j < 4; j++) acc[i][j] = 0.f;

    do_load(0);
    do_store(0);
    __syncthreads();

    for (int kc = 0; kc < 32; kc++) {
        int buf = kc & 1;
        if (kc + 1 < 32) do_load(kc + 1);
        const float* aB = &sA[buf][(wm * 16 + gq) * LDS];
        #pragma unroll
        for (int k8 = 0; k8 < 4; k8++) {
            int kk = k8 * 8;
            float af[4];
            af[0] = aB[kk + tig];
            af[1] = aB[8 * LDS + kk + tig];
            af[2] = aB[kk + tig + 4];
            af[3] = aB[8 * LDS + kk + tig + 4];
            #pragma unroll
            for (int nt = 0; nt < 4; nt++) {
                int nl = wn * 32 + nt * 8 + gq;
                float bf[2];
                bf[0] = sW[buf][nl * LDS + kk + tig];
                bf[1] = sW[buf][nl * LDS + kk + tig + 4];
                mma8(acc[nt], af, bf);
            }
        }
        if (kc + 1 < 32) do_store(buf ^ 1);
        __syncthreads();
    }

    // scatter D + bias directly to g_G0 ([T][dir][B][4096])
    int b = mtile >> 3, tb = (mtile & 7) * 64;
    int ncd = (ntile & 63) * 64 + wn * 32;
    int r0 = wm * 16 + gq;
    #pragma unroll
    for (int nt = 0; nt < 4; nt++) {
        int cc = ncd + nt * 8 + tig * 2;
        float bs0 = g_bsum[dir][cc], bs1 = g_bsum[dir][cc + 1];
        size_t d0 = ((size_t)((tb + r0) * 2 + dir) * 64 + b) * (size_t)G4 + cc;
        size_t d2 = ((size_t)((tb + r0 + 8) * 2 + dir) * 64 + b) * (size_t)G4 + cc;
        g_G0[d0] = acc[nt][0] + bs0;
        g_G0[d0 + 1] = acc[nt][1] + bs1;
        g_G0[d2] = acc[nt][2] + bs0;
        g_G0[d2 + 1] = acc[nt][3] + bs1;
    }
}

__global__ void bsum_kernel(const float* __restrict__ bih_f, const float* __restrict__ bhh_f,
                            const float* __restrict__ bih_b, const float* __restrict__ bhh_b) {
    int i = blockIdx.x * 256 + threadIdx.x;
    if (i < 4096) {
        g_bsum[0][i] = bih_f[i] + bhh_f[i];
        g_bsum[2][i] = bih_f[4096 + i] + bhh_f[4096 + i];
        g_bsum[1][i] = bih_b[i] + bhh_b[i];
        g_bsum[3][i] = bih_b[4096 + i] + bhh_b[4096 + i];
    }
}

__global__ void zero_kernel() {
    int i = blockIdx.x * 256 + threadIdx.x;
    if (i < 2 * BSZ * HDIM) {
        (&g_h0[0][0])[i] = 0.f;
        (&g_c0[0][0])[i] = 0.f;
        (&g_h1[0][0])[i] = 0.f;
        (&g_c1[0][0])[i] = 0.f;
    }
}

extern "C" void kernel_launch(void* const* d_in, const int* in_sizes, int n_in,
                              void* d_out, int out_size) {
    const float* x     = (const float*)d_in[0];
    const float* Wih_f = (const float*)d_in[1];
    const float* Whh_f = (const float*)d_in[2];
    const float* bih_f = (const float*)d_in[3];
    const float* bhh_f = (const float*)d_in[4];
    const float* Wih_b = (const float*)d_in[5];
    const float* Whh_b = (const float*)d_in[6];
    const float* bih_b = (const float*)d_in[7];
    const float* bhh_b = (const float*)d_in[8];
    float* out = (float*)d_out;

    bsum_kernel<<<16, 256>>>(bih_f, bhh_f, bih_b, bhh_b);
    zero_kernel<<<512, 256>>>();
    g0_kernel<<<65536, 256>>>(x, Wih_f, Wih_b);
    scan_kernel<<<NBLK, 256>>>(Wih_f, Whh_f, Wih_b, Whh_b, out);
}

// round 3
// speedup vs baseline: 1.0654x; 1.0654x over previous
#include <cuda_runtime.h>
#include <cstdint>

#define HDIM 1024
#define BSZ 64
#define TLEN 512
#define G4 4096
#define KC 32
#define LDS 36
#define NBLK 128
#define STAGES 4
#define STGF (64 * LDS)          // 2304 floats per matrix per stage
#define SMEM_FLOATS (2 * STAGES * STGF + 4096)
#define SMEM_BYTES (SMEM_FLOATS * 4)

// scratch (device statics; no allocations)
__device__ float g_G0[268435456];          // [T][dir][B][4096] precomputed x-gates (+bias), 1 GiB
__device__ float g_bsum[4][G4];            // bias sums: f0, b0, f1, b1
__device__ float g_h0[2][BSZ * HDIM];      // layer0 carried h (backward), ping-pong (tf32-rounded)
__device__ float g_c0[2][BSZ * HDIM];
__device__ float g_h1[2][BSZ * HDIM];      // layer1 carried h (backward), ping-pong (tf32-rounded)
__device__ float g_c1[2][BSZ * HDIM];
__device__ float g_hf0[2][BSZ * HDIM];     // layer0 forward h, ping-pong (tf32-rounded)
__device__ unsigned g_gen;
__device__ unsigned g_cnt;

__device__ __forceinline__ float f2tf32(float x) {
    unsigned u;
    asm("cvt.rna.tf32.f32 %0, %1;" : "=r"(u) : "f"(x));
    return __uint_as_float(u);
}

__device__ __forceinline__ void mma8(float acc[4], const float a[4], const float b[2]) {
    const unsigned* A = reinterpret_cast<const unsigned*>(a);
    const unsigned* B = reinterpret_cast<const unsigned*>(b);
    asm volatile(
        "mma.sync.aligned.m16n8k8.row.col.f32.tf32.tf32.f32 "
        "{%0,%1,%2,%3}, {%4,%5,%6,%7}, {%8,%9}, {%0,%1,%2,%3};\n"
        : "+f"(acc[0]), "+f"(acc[1]), "+f"(acc[2]), "+f"(acc[3])
        : "r"(A[0]), "r"(A[1]), "r"(A[2]), "r"(A[3]), "r"(B[0]), "r"(B[1]));
}

__device__ __forceinline__ float sigf(float x) { return 1.0f / (1.0f + expf(-x)); }

__device__ __forceinline__ void cp16(void* dst, const void* src) {
    unsigned d = (unsigned)__cvta_generic_to_shared(dst);
    asm volatile("cp.async.cg.shared.global [%0], [%1], 16;" :: "r"(d), "l"(src));
}
#define CP_COMMIT() asm volatile("cp.async.commit_group;")
#define CP_WAIT(n)  asm volatile("cp.async.wait_group %0;" :: "n"(n))

__device__ __forceinline__ float4 cvt4(float4 v) {
    v.x = f2tf32(v.x); v.y = f2tf32(v.y); v.z = f2tf32(v.z); v.w = f2tf32(v.w);
    return v;
}

// Software grid barrier. Safe: 128 blocks <= 148 SMs, all co-resident.
__device__ __forceinline__ void grid_bar() {
    __syncthreads();
    if (threadIdx.x == 0) {
        volatile unsigned* vg = &g_gen;
        unsigned gen = *vg;
        __threadfence();                       // release
        if (atomicAdd(&g_cnt, 1u) == NBLK - 1) {
            g_cnt = 0;
            __threadfence();
            *vg = gen + 1;
        } else {
            while (*vg == gen) { __nanosleep(20); }
        }
        __threadfence();                       // acquire (CCTL.IVALL -> fresh L1)
    }
    __syncthreads();
}

// ---------------------------------------------------------------------------
// One GEMM+LSTM phase of the scan.
// mode 1: layer0  gates = G0[t] + h_prev0 @ Whh0^T           (K=1024)
// mode 2: layer1  gates = h_in @ Wih1^T + h_prev1 @ Whh1^T   (K=2048)
// Block computes M=64 (batch) x N=64 (4 gates x 16 units at n0).
// Global->smem via 4-stage cp.async pipeline (raw fp32; HMMA truncates to tf32;
// the recurrent h values are RNA-rounded to tf32 at store time).
// ---------------------------------------------------------------------------
__device__ __forceinline__ void scan_phase(
    int mode, int t, int dir, int n0,
    const float* __restrict__ Wih_f, const float* __restrict__ Whh_f,
    const float* __restrict__ Wih_b, const float* __restrict__ Whh_b,
    float* __restrict__ dout,
    float* sA, float* sW, float* sG)
{
    const int tid = threadIdx.x;
    const int p = t & 1;

    const float *A0, *A1, *W0, *W1;
    int nkc;
    if (mode == 1) {
        A0 = A1 = g_h0[p];
        W0 = W1 = dir ? Whh_b : Whh_f;
        nkc = 32;
    } else {
        A0 = dir ? g_h0[1 - p] : g_hf0[1 - p];
        A1 = g_h1[p];
        W0 = (dir ? Wih_b : Wih_f) + (size_t)G4 * HDIM;
        W1 = (dir ? Whh_b : Whh_f) + (size_t)G4 * HDIM;
        nkc = 64;
    }

    const int rowA0 = tid >> 3, kq = tid & 7, rowA1 = rowA0 + 32;
    const int wr0 = ((rowA0 >> 4) << 10) + n0 + (rowA0 & 15);
    const int wr1 = ((rowA1 >> 4) << 10) + n0 + (rowA1 & 15);

    // G0 tile prefetch (phase 1 only): its own cp.async group, issued first.
    if (mode == 1) {
        int mRow = tid >> 2, g = tid & 3;
        const float* src = g_G0 + ((size_t)(2 * t + dir) * 64 + mRow) * (size_t)G4 + g * HDIM + n0;
        float* dst = sG + mRow * 64 + g * 16;
        cp16(dst, src); cp16(dst + 4, src + 4); cp16(dst + 8, src + 8); cp16(dst + 12, src + 12);
        CP_COMMIT();
    }

    auto issue = [&](int kc, int buf) {
        if (kc < nkc) {
            int sel = kc >= 32;
            const float* Ap = sel ? A1 : A0;
            const float* Wp = sel ? W1 : W0;
            int kl = (kc & 31) * KC + kq * 4;
            float* dA = sA + buf * STGF;
            float* dW = sW + buf * STGF;
            cp16(dA + rowA0 * LDS + kq * 4, Ap + (size_t)rowA0 * HDIM + kl);
            cp16(dA + rowA1 * LDS + kq * 4, Ap + (size_t)rowA1 * HDIM + kl);
            cp16(dW + rowA0 * LDS + kq * 4, Wp + (size_t)wr0 * HDIM + kl);
            cp16(dW + rowA1 * LDS + kq * 4, Wp + (size_t)wr1 * HDIM + kl);
        }
        CP_COMMIT();
    };

    const int wid = tid >> 5, lane = tid & 31;
    const int wm = wid & 3, wn = wid >> 2;      // warp tile: 16 rows x 32 cols
    const int gq = lane >> 2, tig = lane & 3;

    float acc[4][4];
    #pragma unroll
    for (int i = 0; i < 4; i++)
        #pragma unroll
        for (int j = 0; j < 4; j++) acc[i][j] = 0.f;

    #pragma unroll
    for (int s = 0; s < STAGES - 1; s++) issue(s, s);

    for (int kc = 0; kc < nkc; kc++) {
        CP_WAIT(STAGES - 2);
        __syncthreads();
        issue(kc + STAGES - 1, (kc + STAGES - 1) & (STAGES - 1));
        int buf = kc & (STAGES - 1);
        const float* aB = sA + buf * STGF + (wm * 16 + gq) * LDS;
        const float* wB = sW + buf * STGF;
        #pragma unroll
        for (int k8 = 0; k8 < 4; k8++) {
            int kk = k8 * 8;
            float af[4];
            af[0] = aB[kk + tig];
            af[1] = aB[8 * LDS + kk + tig];
            af[2] = aB[kk + tig + 4];
            af[3] = aB[8 * LDS + kk + tig + 4];
            #pragma unroll
            for (int nt = 0; nt < 4; nt++) {
                int nl = wn * 32 + nt * 8 + gq;
                float bf[2];
                bf[0] = wB[nl * LDS + kk + tig];
                bf[1] = wB[nl * LDS + kk + tig + 4];
                mma8(acc[nt], af, bf);
            }
        }
    }
    CP_WAIT(0);
    __syncthreads();

    // gather accumulators so each thread sees all 4 gates of one (batch, unit)
    float* gsm = sA;   // reuse stage area as 64 x 65
    {
        int r0 = wm * 16 + gq;
        #pragma unroll
        for (int nt = 0; nt < 4; nt++) {
            int cc = wn * 32 + nt * 8 + tig * 2;
            gsm[r0 * 65 + cc] = acc[nt][0];
            gsm[r0 * 65 + cc + 1] = acc[nt][1];
            gsm[(r0 + 8) * 65 + cc] = acc[nt][2];
            gsm[(r0 + 8) * 65 + cc + 1] = acc[nt][3];
        }
    }
    __syncthreads();

    #pragma unroll
    for (int r = 0; r < 4; r++) {
        int idx = tid + 256 * r;
        int m = idx >> 4, j = idx & 15;
        float gi = gsm[m * 65 + j];
        float gf = gsm[m * 65 + 16 + j];
        float gg = gsm[m * 65 + 32 + j];
        float go = gsm[m * 65 + 48 + j];
        int n = n0 + j;
        int hi = m * HDIM + n;
        if (mode == 1) {
            gi += sG[m * 64 + j];
            gf += sG[m * 64 + 16 + j];
            gg += sG[m * 64 + 32 + j];
            go += sG[m * 64 + 48 + j];
            float cp = g_c0[p][hi];
            float c2 = sigf(gf) * cp + sigf(gi) * tanhf(gg);
            float h2 = sigf(go) * tanhf(c2);
            if (dir == 0) {
                g_hf0[1 - p][hi] = f2tf32(h2);
            } else {
                g_h0[1 - p][hi] = f2tf32(h2);
                g_c0[1 - p][hi] = c2;
            }
        } else {
            gi += g_bsum[2 + dir][n];
            gf += g_bsum[2 + dir][HDIM + n];
            gg += g_bsum[2 + dir][2 * HDIM + n];
            go += g_bsum[2 + dir][3 * HDIM + n];
            float cp = g_c1[p][hi];
            float c2 = sigf(gf) * cp + sigf(gi) * tanhf(gg);
            float h2 = sigf(go) * tanhf(c2);
            size_t ob = ((size_t)m * TLEN + t) * 2048 + (size_t)dir * HDIM + n;
            __stcs(&dout[ob], h2);                           // out
            __stcs(&dout[67108864 + ob], c2);                // c_out
            if (t == TLEN - 1) {
                size_t lb = (size_t)m * 2048 + (size_t)dir * HDIM + n;
                dout[134217728 + lb] = h2;                   // out[:, -1]
                dout[134217728 + 131072 + lb] = c2;          // c_out[:, -1]
            }
            if (dir == 1) {
                g_h1[1 - p][hi] = f2tf32(h2);
                g_c1[1 - p][hi] = c2;
            }
        }
    }
    __syncthreads();   // protect smem before next phase's prologue
}

// Persistent scan kernel: entire 512-step recurrence in ONE launch.
__global__ __launch_bounds__(256, 1) void scan_kernel(
    const float* __restrict__ Wih_f, const float* __restrict__ Whh_f,
    const float* __restrict__ Wih_b, const float* __restrict__ Whh_b,
    float* __restrict__ dout)
{
    extern __shared__ float smem[];
    float* sA = smem;
    float* sW = smem + STAGES * STGF;
    float* sG = smem + 2 * STAGES * STGF;

    const int bx = blockIdx.x;
    const int dir = bx >> 6;
    const int n0 = (bx & 63) * 16;

    for (int t = 0; t < TLEN; t++) {
        scan_phase(1, t, dir, n0, Wih_f, Whh_f, Wih_b, Whh_b, dout, sA, sW, sG);
        grid_bar();
        scan_phase(2, t, dir, n0, Wih_f, Whh_f, Wih_b, Whh_b, dout, sA, sW, sG);
        // phase1(t+1) touches only parity-p buffers which in-flight phase2(t)
        // never reads; the t+1 barrier fences everything else.
    }
}

// Precompute G0 = x @ Wih0^T (+ bias sums), both directions (feature-reversed
// A-loads for backward). M = B*T = 32768, N = 2 x 4096, K = 1024.
__global__ __launch_bounds__(256) void g0_kernel(
    const float* __restrict__ x,
    const float* __restrict__ Wih_f, const float* __restrict__ Wih_b)
{
    __shared__ float sA[2][64 * LDS];
    __shared__ float sW[2][64 * LDS];

    const int tid = threadIdx.x;
    const int bx = blockIdx.x;
    const int mtile = bx >> 7;
    const int ntile = bx & 127;
    const int dir = ntile >> 6;
    const bool revA = (dir == 1);
    const float* Ap = x + (size_t)mtile * 64 * HDIM;
    const float* Wp = dir ? Wih_b : Wih_f;
    const int wrowbase = (ntile & 63) * 64;

    const int rowA0 = tid >> 3, kq = tid & 7, rowA1 = rowA0 + 32;
    const int wr0 = wrowbase + rowA0;
    const int wr1 = wrowbase + rowA1;

    float4 ra0, ra1, rw0, rw1;
    auto do_load = [&](int kc) {
        int kl = kc * KC + kq * 4;
        if (!revA) {
            ra0 = *(const float4*)(Ap + (size_t)rowA0 * HDIM + kl);
            ra1 = *(const float4*)(Ap + (size_t)rowA1 * HDIM + kl);
        } else {
            ra0 = *(const float4*)(Ap + (size_t)rowA0 * HDIM + (HDIM - 4) - kl);
            ra1 = *(const float4*)(Ap + (size_t)rowA1 * HDIM + (HDIM - 4) - kl);
        }
        rw0 = *(const float4*)(Wp + (size_t)wr0 * HDIM + kl);
        rw1 = *(const float4*)(Wp + (size_t)wr1 * HDIM + kl);
    };
    auto rev4 = [](float4 v) { float4 r; r.x = v.w; r.y = v.z; r.z = v.y; r.w = v.x; return r; };
    auto do_store = [&](int buf) {
        float4 a0 = cvt4(ra0), a1 = cvt4(ra1);
        if (revA) { a0 = rev4(a0); a1 = rev4(a1); }
        *(float4*)(&sA[buf][rowA0 * LDS + kq * 4]) = a0;
        *(float4*)(&sA[buf][rowA1 * LDS + kq * 4]) = a1;
        *(float4*)(&sW[buf][rowA0 * LDS + kq * 4]) = cvt4(rw0);
        *(float4*)(&sW[buf][rowA1 * LDS + kq * 4]) = cvt4(rw1);
    };

    const int wid = tid >> 5, lane = tid & 31;
    const int wm = wid & 3, wn = wid >> 2;
    const int gq = lane >> 2, tig = lane & 3;

    float acc[4][4];
    #pragma unroll
    for (int i = 0; i < 4; i++)
        #pragma unroll
        for (int j = 0; j < 4; j++) acc[i][j] = 0.f;

    do_load(0);
    do_store(0);
    __syncthreads();

    for (int kc = 0; kc < 32; kc++) {
        int buf = kc & 1;
        if (kc + 1 < 32) do_load(kc + 1);
        const float* aB = &sA[buf][(wm * 16 + gq) * LDS];
        #pragma unroll
        for (int k8 = 0; k8 < 4; k8++) {
            int kk = k8 * 8;
            float af[4];
            af[0] = aB[kk + tig];
            af[1] = aB[8 * LDS + kk + tig];
            af[2] = aB[kk + tig + 4];
            af[3] = aB[8 * LDS + kk + tig + 4];
            #pragma unroll
            for (int nt = 0; nt < 4; nt++) {
                int nl = wn * 32 + nt * 8 + gq;
                float bf[2];
                bf[0] = sW[buf][nl * LDS + kk + tig];
                bf[1] = sW[buf][nl * LDS + kk + tig + 4];
                mma8(acc[nt], af, bf);
            }
        }
        if (kc + 1 < 32) do_store(buf ^ 1);
        __syncthreads();
    }

    // scatter D + bias directly to g_G0 ([T][dir][B][4096]), streaming stores
    int b = mtile >> 3, tb = (mtile & 7) * 64;
    int ncd = (ntile & 63) * 64 + wn * 32;
    int r0 = wm * 16 + gq;
    #pragma unroll
    for (int nt = 0; nt < 4; nt++) {
        int cc = ncd + nt * 8 + tig * 2;
        float bs0 = g_bsum[dir][cc], bs1 = g_bsum[dir][cc + 1];
        size_t d0 = ((size_t)((tb + r0) * 2 + dir) * 64 + b) * (size_t)G4 + cc;
        size_t d2 = ((size_t)((tb + r0 + 8) * 2 + dir) * 64 + b) * (size_t)G4 + cc;
        __stcs(&g_G0[d0], acc[nt][0] + bs0);
        __stcs(&g_G0[d0 + 1], acc[nt][1] + bs1);
        __stcs(&g_G0[d2], acc[nt][2] + bs0);
        __stcs(&g_G0[d2 + 1], acc[nt][3] + bs1);
    }
}

__global__ void bsum_kernel(const float* __restrict__ bih_f, const float* __restrict__ bhh_f,
                            const float* __restrict__ bih_b, const float* __restrict__ bhh_b) {
    int i = blockIdx.x * 256 + threadIdx.x;
    if (i < 4096) {
        g_bsum[0][i] = bih_f[i] + bhh_f[i];
        g_bsum[2][i] = bih_f[4096 + i] + bhh_f[4096 + i];
        g_bsum[1][i] = bih_b[i] + bhh_b[i];
        g_bsum[3][i] = bih_b[4096 + i] + bhh_b[4096 + i];
    }
}

__global__ void zero_kernel() {
    int i = blockIdx.x * 256 + threadIdx.x;
    if (i < 2 * BSZ * HDIM) {
        (&g_h0[0][0])[i] = 0.f;
        (&g_c0[0][0])[i] = 0.f;
        (&g_h1[0][0])[i] = 0.f;
        (&g_c1[0][0])[i] = 0.f;
    }
}

extern "C" void kernel_launch(void* const* d_in, const int* in_sizes, int n_in,
                              void* d_out, int out_size) {
    const float* x     = (const float*)d_in[0];
    const float* Wih_f = (const float*)d_in[1];
    const float* Whh_f = (const float*)d_in[2];
    const float* bih_f = (const float*)d_in[3];
    const float* bhh_f = (const float*)d_in[4];
    const float* Wih_b = (const float*)d_in[5];
    const float* Whh_b = (const float*)d_in[6];
    const float* bih_b = (const float*)d_in[7];
    const float* bhh_b = (const float*)d_in[8];
    float* out = (float*)d_out;

    static bool attr_set = false;
    if (!attr_set) {
        cudaFuncSetAttribute(scan_kernel, cudaFuncAttributeMaxDynamicSharedMemorySize, SMEM_BYTES);
        attr_set = true;
    }

    bsum_kernel<<<16, 256>>>(bih_f, bhh_f, bih_b, bhh_b);
    zero_kernel<<<512, 256>>>();
    g0_kernel<<<65536, 256>>>(x, Wih_f, Wih_b);
    scan_kernel<<<NBLK, 256, SMEM_BYTES>>>(Wih_f, Whh_f, Wih_b, Whh_b, out);
}

// round 4
// speedup vs baseline: 1.6651x; 1.5629x over previous
#include <cuda_runtime.h>
#include <cstdint>

#define HDIM 1024
#define BSZ 64
#define TLEN 512
#define G4 4096
#define KC 32
#define LDS 36
#define NBLK 128
#define STAGES 6
#define STGF (64 * LDS)          // 2304 floats per matrix per stage
#define SMEM_FLOATS (2 * STAGES * STGF + 4096)
#define SMEM_BYTES (SMEM_FLOATS * 4)

// scratch (device statics; no allocations)
__device__ float g_G0[268435456];          // [T][dir][B][4096] precomputed x-gates (+bias), 1 GiB
__device__ float g_Wp1[33554432];          // packed phase1 weights [dir][nb][64][1024]   (33.5 MB)
__device__ float g_Wp2[67108864];          // packed phase2 weights [dir][nb][64][2048]   (67 MB)
__device__ float g_bsum[4][G4];            // bias sums: f0, b0, f1, b1
__device__ float g_h0[2][BSZ * HDIM];      // layer0 carried h (backward), ping-pong (tf32-rounded)
__device__ float g_c0[2][BSZ * HDIM];
__device__ float g_h1[2][BSZ * HDIM];      // layer1 carried h (backward), ping-pong (tf32-rounded)
__device__ float g_c1[2][BSZ * HDIM];
__device__ float g_hf0[2][BSZ * HDIM];     // layer0 forward h, ping-pong
__device__ unsigned g_gen;
__device__ unsigned g_cnt;

__device__ __forceinline__ float f2tf32(float x) {
    unsigned u;
    asm("cvt.rna.tf32.f32 %0, %1;" : "=r"(u) : "f"(x));
    return __uint_as_float(u);
}

__device__ __forceinline__ void mma8(float acc[4], const float a[4], const float b[2]) {
    const unsigned* A = reinterpret_cast<const unsigned*>(a);
    const unsigned* B = reinterpret_cast<const unsigned*>(b);
    asm volatile(
        "mma.sync.aligned.m16n8k8.row.col.f32.tf32.tf32.f32 "
        "{%0,%1,%2,%3}, {%4,%5,%6,%7}, {%8,%9}, {%0,%1,%2,%3};\n"
        : "+f"(acc[0]), "+f"(acc[1]), "+f"(acc[2]), "+f"(acc[3])
        : "r"(A[0]), "r"(A[1]), "r"(A[2]), "r"(A[3]), "r"(B[0]), "r"(B[1]));
}

// fast, overflow-safe activations (__expf rel err ~1e-7: negligible here)
__device__ __forceinline__ float sigf(float x) {
    return __fdividef(1.0f, 1.0f + __expf(-x));
}
__device__ __forceinline__ float tanh_(float x) {
    float a = fabsf(x);
    float e = __expf(-2.0f * a);
    float r = __fdividef(1.0f - e, 1.0f + e);
    return copysignf(r, x);
}

__device__ __forceinline__ uint64_t mkpol_last() {
    uint64_t p;
    asm("createpolicy.fractional.L2::evict_last.b64 %0, 1.0;" : "=l"(p));
    return p;
}
__device__ __forceinline__ uint64_t mkpol_first() {
    uint64_t p;
    asm("createpolicy.fractional.L2::evict_first.b64 %0, 1.0;" : "=l"(p));
    return p;
}
__device__ __forceinline__ void cp16(void* dst, const void* src) {
    unsigned d = (unsigned)__cvta_generic_to_shared(dst);
    asm volatile("cp.async.cg.shared.global [%0], [%1], 16;" :: "r"(d), "l"(src));
}
__device__ __forceinline__ void cp16p(void* dst, const void* src, uint64_t pol) {
    unsigned d = (unsigned)__cvta_generic_to_shared(dst);
    asm volatile("cp.async.cg.shared.global.L2::cache_hint [%0], [%1], 16, %2;"
                 :: "r"(d), "l"(src), "l"(pol));
}
#define CP_COMMIT() asm volatile("cp.async.commit_group;")
#define CP_WAIT(n)  asm volatile("cp.async.wait_group %0;" :: "n"(n))

__device__ __forceinline__ float4 cvt4(float4 v) {
    v.x = f2tf32(v.x); v.y = f2tf32(v.y); v.z = f2tf32(v.z); v.w = f2tf32(v.w);
    return v;
}

// Software grid barrier. Safe: 128 blocks <= 148 SMs, all co-resident.
__device__ __forceinline__ void grid_bar() {
    __syncthreads();
    if (threadIdx.x == 0) {
        volatile unsigned* vg = &g_gen;
        unsigned gen = *vg;
        __threadfence();                       // release
        if (atomicAdd(&g_cnt, 1u) == NBLK - 1) {
            g_cnt = 0;
            __threadfence();
            *vg = gen + 1;
        } else {
            while (*vg == gen) { __nanosleep(20); }
        }
        __threadfence();                       // acquire
    }
    __syncthreads();
}

// ---------------------------------------------------------------------------
// One GEMM+LSTM phase of the scan.
// mode 1: layer0  gates = G0[t] + h_prev0 @ Whh0^T           (32 chunks, packed W stride 1024)
// mode 2: layer1  gates = h_in @ Wih1^T + h_prev1 @ Whh1^T   (64 chunks, packed W stride 2048)
// Block computes M=64 (batch) x N=64 (4 gates x 16 units).
// ---------------------------------------------------------------------------
__device__ __forceinline__ void scan_phase(
    int mode, int t, int dir, int nblk,
    float* __restrict__ dout,
    float* sA, float* sW, float* sG,
    uint64_t polL, uint64_t polF)
{
    const int tid = threadIdx.x;
    const int p = t & 1;
    const int n0 = nblk * 16;

    const float *A0, *A1, *Wb;
    int nkc, wstride;
    if (mode == 1) {
        A0 = A1 = g_h0[p];
        Wb = g_Wp1 + (size_t)(dir * 64 + nblk) * 64 * 1024;
        wstride = 1024;
        nkc = 32;
    } else {
        A0 = dir ? g_h0[1 - p] : g_hf0[1 - p];
        A1 = g_h1[p];
        Wb = g_Wp2 + (size_t)(dir * 64 + nblk) * 64 * 2048;
        wstride = 2048;
        nkc = 64;
    }

    const int rowA0 = tid >> 3, kq = tid & 7, rowA1 = rowA0 + 32;

    // G0 tile prefetch (phase 1 only): its own cp.async group, issued first.
    if (mode == 1) {
        int mRow = tid >> 2, g = tid & 3;
        const float* src = g_G0 + ((size_t)(2 * t + dir) * 64 + mRow) * (size_t)G4 + g * HDIM + n0;
        float* dst = sG + mRow * 64 + g * 16;
        cp16p(dst, src, polF); cp16p(dst + 4, src + 4, polF);
        cp16p(dst + 8, src + 8, polF); cp16p(dst + 12, src + 12, polF);
        CP_COMMIT();
    }

    auto issue = [&](int kc, int buf) {
        if (kc < nkc) {
            const float* Ap = (kc >= 32) ? A1 : A0;
            int klA = (kc & 31) * KC + kq * 4;
            int klW = kc * KC + kq * 4;
            float* dA = sA + buf * STGF;
            float* dW = sW + buf * STGF;
            cp16(dA + rowA0 * LDS + kq * 4, Ap + (size_t)rowA0 * HDIM + klA);
            cp16(dA + rowA1 * LDS + kq * 4, Ap + (size_t)rowA1 * HDIM + klA);
            cp16p(dW + rowA0 * LDS + kq * 4, Wb + (size_t)rowA0 * wstride + klW, polL);
            cp16p(dW + rowA1 * LDS + kq * 4, Wb + (size_t)rowA1 * wstride + klW, polL);
        }
        CP_COMMIT();
    };

    const int wid = tid >> 5, lane = tid & 31;
    const int wm = wid & 3, wn = wid >> 2;      // warp tile: 16 rows x 32 cols
    const int gq = lane >> 2, tig = lane & 3;

    float acc[4][4];
    #pragma unroll
    for (int i = 0; i < 4; i++)
        #pragma unroll
        for (int j = 0; j < 4; j++) acc[i][j] = 0.f;

    #pragma unroll
    for (int s = 0; s < STAGES - 1; s++) issue(s, s);

    for (int kc = 0; kc < nkc; kc++) {
        CP_WAIT(STAGES - 2);
        __syncthreads();
        int nb = kc + STAGES - 1;
        issue(nb, nb % STAGES);
        int buf = kc % STAGES;
        const float* aB = sA + buf * STGF + (wm * 16 + gq) * LDS;
        const float* wB = sW + buf * STGF;
        #pragma unroll
        for (int k8 = 0; k8 < 4; k8++) {
            int kk = k8 * 8;
            float af[4];
            af[0] = aB[kk + tig];
            af[1] = aB[8 * LDS + kk + tig];
            af[2] = aB[kk + tig + 4];
            af[3] = aB[8 * LDS + kk + tig + 4];
            #pragma unroll
            for (int nt = 0; nt < 4; nt++) {
                int nl = wn * 32 + nt * 8 + gq;
                float bf[2];
                bf[0] = wB[nl * LDS + kk + tig];
                bf[1] = wB[nl * LDS + kk + tig + 4];
                mma8(acc[nt], af, bf);
            }
        }
    }
    CP_WAIT(0);
    __syncthreads();

    // gather accumulators so each thread sees all 4 gates of one (batch, unit)
    float* gsm = sA;   // reuse stage area as 64 x 65
    {
        int r0 = wm * 16 + gq;
        #pragma unroll
        for (int nt = 0; nt < 4; nt++) {
            int cc = wn * 32 + nt * 8 + tig * 2;
            gsm[r0 * 65 + cc] = acc[nt][0];
            gsm[r0 * 65 + cc + 1] = acc[nt][1];
            gsm[(r0 + 8) * 65 + cc] = acc[nt][2];
            gsm[(r0 + 8) * 65 + cc + 1] = acc[nt][3];
        }
    }
    __syncthreads();

    #pragma unroll
    for (int r = 0; r < 4; r++) {
        int idx = tid + 256 * r;
        int m = idx >> 4, j = idx & 15;
        float gi = gsm[m * 65 + j];
        float gf = gsm[m * 65 + 16 + j];
        float gg = gsm[m * 65 + 32 + j];
        float go = gsm[m * 65 + 48 + j];
        int n = n0 + j;
        int hi = m * HDIM + n;
        if (mode == 1) {
            gi += sG[m * 64 + j];
            gf += sG[m * 64 + 16 + j];
            gg += sG[m * 64 + 32 + j];
            go += sG[m * 64 + 48 + j];
            float cp = g_c0[p][hi];
            float c2 = sigf(gf) * cp + sigf(gi) * tanh_(gg);
            float h2 = sigf(go) * tanh_(c2);
            if (dir == 0) {
                g_hf0[1 - p][hi] = f2tf32(h2);
            } else {
                g_h0[1 - p][hi] = f2tf32(h2);
                g_c0[1 - p][hi] = c2;
            }
        } else {
            gi += g_bsum[2 + dir][n];
            gf += g_bsum[2 + dir][HDIM + n];
            gg += g_bsum[2 + dir][2 * HDIM + n];
            go += g_bsum[2 + dir][3 * HDIM + n];
            float cp = g_c1[p][hi];
            float c2 = sigf(gf) * cp + sigf(gi) * tanh_(gg);
            float h2 = sigf(go) * tanh_(c2);
            size_t ob = ((size_t)m * TLEN + t) * 2048 + (size_t)dir * HDIM + n;
            __stcs(&dout[ob], h2);                           // out
            __stcs(&dout[67108864 + ob], c2);                // c_out
            if (t == TLEN - 1) {
                size_t lb = (size_t)m * 2048 + (size_t)dir * HDIM + n;
                dout[134217728 + lb] = h2;                   // out[:, -1]
                dout[134217728 + 131072 + lb] = c2;          // c_out[:, -1]
            }
            if (dir == 1) {
                g_h1[1 - p][hi] = f2tf32(h2);
                g_c1[1 - p][hi] = c2;
            }
        }
    }
    __syncthreads();   // protect smem before next phase's prologue
}

// Persistent scan kernel: entire 512-step recurrence in ONE launch.
__global__ __launch_bounds__(256, 1) void scan_kernel(float* __restrict__ dout)
{
    extern __shared__ float smem[];
    float* sA = smem;
    float* sW = smem + STAGES * STGF;
    float* sG = smem + 2 * STAGES * STGF;

    const int bx = blockIdx.x;
    const int dir = bx >> 6;
    const int nblk = bx & 63;
    const uint64_t polL = mkpol_last();
    const uint64_t polF = mkpol_first();

    for (int t = 0; t < TLEN; t++) {
        scan_phase(1, t, dir, nblk, dout, sA, sW, sG, polL, polF);
        grid_bar();
        scan_phase(2, t, dir, nblk, dout, sA, sW, sG, polL, polF);
        // phase1(t+1) touches only parity buffers in-flight phase2(t) never
        // reads; the t+1 barrier fences everything else.
    }
}

// Repack the 6 scan weight matrices into per-block-contiguous strips.
// g_Wp1[dir][nb][row(64)][1024] = Whh{dir} layer0, rows g*1024+nb*16+u
// g_Wp2[dir][nb][row(64)][2048] = [Wih{dir} layer1 | Whh{dir} layer1]
__global__ void pack_kernel(
    const float* __restrict__ Whh_f, const float* __restrict__ Whh_b,
    const float* __restrict__ Wih_f, const float* __restrict__ Wih_b)
{
    int id = blockIdx.x * 256 + threadIdx.x;     // one float4 each
    if (id < 2097152) {                          // g_Wp1: 2 * 2^20 float4
        int dir = id >> 20;
        int r2 = id & 1048575;
        int nb = r2 >> 14;
        int r3 = r2 & 16383;
        int row = r3 >> 8;
        int kq = r3 & 255;
        int grow = (row >> 4) * 1024 + nb * 16 + (row & 15);
        const float* src = (dir ? Whh_b : Whh_f) + (size_t)grow * 1024 + kq * 4;
        float4 v = __ldcs((const float4*)src);
        *(float4*)(g_Wp1 + (size_t)id * 4) = v;
    } else {
        int id2 = id - 2097152;                  // g_Wp2: 2 * 2^21 float4
        if (id2 >= 4194304) return;
        int dir = id2 >> 21;
        int r2 = id2 & 2097151;
        int nb = r2 >> 15;
        int r3 = r2 & 32767;
        int row = r3 >> 9;
        int kq = r3 & 511;
        int k = kq * 4;
        int grow = (row >> 4) * 1024 + nb * 16 + (row & 15);
        const float* base = (k < 1024) ? ((dir ? Wih_b : Wih_f) + 4194304)
                                       : ((dir ? Whh_b : Whh_f) + 4194304);
        const float* src = base + (size_t)grow * 1024 + (k & 1023);
        float4 v = __ldcs((const float4*)src);
        *(float4*)(g_Wp2 + (size_t)id2 * 4) = v;
    }
}

// Precompute G0 = x @ Wih0^T (+ bias sums), both directions (feature-reversed
// A-loads for backward). M = B*T = 32768, N = 2 x 4096, K = 1024.
__global__ __launch_bounds__(256) void g0_kernel(
    const float* __restrict__ x,
    const float* __restrict__ Wih_f, const float* __restrict__ Wih_b)
{
    __shared__ float sA[2][64 * LDS];
    __shared__ float sW[2][64 * LDS];

    const int tid = threadIdx.x;
    const int bx = blockIdx.x;
    const int mtile = bx >> 7;
    const int ntile = bx & 127;
    const int dir = ntile >> 6;
    const bool revA = (dir == 1);
    const float* Ap = x + (size_t)mtile * 64 * HDIM;
    const float* Wp = dir ? Wih_b : Wih_f;
    const int wrowbase = (ntile & 63) * 64;

    const int rowA0 = tid >> 3, kq = tid & 7, rowA1 = rowA0 + 32;
    const int wr0 = wrowbase + rowA0;
    const int wr1 = wrowbase + rowA1;

    float4 ra0, ra1, rw0, rw1;
    auto do_load = [&](int kc) {
        int kl = kc * KC + kq * 4;
        if (!revA) {
            ra0 = *(const float4*)(Ap + (size_t)rowA0 * HDIM + kl);
            ra1 = *(const float4*)(Ap + (size_t)rowA1 * HDIM + kl);
        } else {
            ra0 = *(const float4*)(Ap + (size_t)rowA0 * HDIM + (HDIM - 4) - kl);
            ra1 = *(const float4*)(Ap + (size_t)rowA1 * HDIM + (HDIM - 4) - kl);
        }
        rw0 = *(const float4*)(Wp + (size_t)wr0 * HDIM + kl);
        rw1 = *(const float4*)(Wp + (size_t)wr1 * HDIM + kl);
    };
    auto rev4 = [](float4 v) { float4 r; r.x = v.w; r.y = v.z; r.z = v.y; r.w = v.x; return r; };
    auto do_store = [&](int buf) {
        float4 a0 = cvt4(ra0), a1 = cvt4(ra1);
        if (revA) { a0 = rev4(a0); a1 = rev4(a1); }
        *(float4*)(&sA[buf][rowA0 * LDS + kq * 4]) = a0;
        *(float4*)(&sA[buf][rowA1 * LDS + kq * 4]) = a1;
        *(float4*)(&sW[buf][rowA0 * LDS + kq * 4]) = cvt4(rw0);
        *(float4*)(&sW[buf][rowA1 * LDS + kq * 4]) = cvt4(rw1);
    };

    const int wid = tid >> 5, lane = tid & 31;
    const int wm = wid & 3, wn = wid >> 2;
    const int gq = lane >> 2, tig = lane & 3;

    float acc[4][4];
    #pragma unroll
    for (int i = 0; i < 4; i++)
        #pragma unroll
        for (int j = 0; j < 4; j++) acc[i][j] = 0.f;

    do_load(0);
    do_store(0);
    __syncthreads();

    for (int kc = 0; kc < 32; kc++) {
        int buf = kc & 1;
        if (kc + 1 < 32) do_load(kc + 1);
        const float* aB = &sA[buf][(wm * 16 + gq) * LDS];
        #pragma unroll
        for (int k8 = 0; k8 < 4; k8++) {
            int kk = k8 * 8;
            float af[4];
            af[0] = aB[kk + tig];
            af[1] = aB[8 * LDS + kk + tig];
            af[2] = aB[kk + tig + 4];
            af[3] = aB[8 * LDS + kk + tig + 4];
            #pragma unroll
            for (int nt = 0; nt < 4; nt++) {
                int nl = wn * 32 + nt * 8 + gq;
                float bf[2];
                bf[0] = sW[buf][nl * LDS + kk + tig];
                bf[1] = sW[buf][nl * LDS + kk + tig + 4];
                mma8(acc[nt], af, bf);
            }
        }
        if (kc + 1 < 32) do_store(buf ^ 1);
        __syncthreads();
    }

    // scatter D + bias directly to g_G0 ([T][dir][B][4096]), streaming stores
    int b = mtile >> 3, tb = (mtile & 7) * 64;
    int ncd = (ntile & 63) * 64 + wn * 32;
    int r0 = wm * 16 + gq;
    #pragma unroll
    for (int nt = 0; nt < 4; nt++) {
        int cc = ncd + nt * 8 + tig * 2;
        float bs0 = g_bsum[dir][cc], bs1 = g_bsum[dir][cc + 1];
        size_t d0 = ((size_t)((tb + r0) * 2 + dir) * 64 + b) * (size_t)G4 + cc;
        size_t d2 = ((size_t)((tb + r0 + 8) * 2 + dir) * 64 + b) * (size_t)G4 + cc;
        __stcs(&g_G0[d0], acc[nt][0] + bs0);
        __stcs(&g_G0[d0 + 1], acc[nt][1] + bs1);
        __stcs(&g_G0[d2], acc[nt][2] + bs0);
        __stcs(&g_G0[d2 + 1], acc[nt][3] + bs1);
    }
}

__global__ void bsum_kernel(const float* __restrict__ bih_f, const float* __restrict__ bhh_f,
                            const float* __restrict__ bih_b, const float* __restrict__ bhh_b) {
    int i = blockIdx.x * 256 + threadIdx.x;
    if (i < 4096) {
        g_bsum[0][i] = bih_f[i] + bhh_f[i];
        g_bsum[2][i] = bih_f[4096 + i] + bhh_f[4096 + i];
        g_bsum[1][i] = bih_b[i] + bhh_b[i];
        g_bsum[3][i] = bih_b[4096 + i] + bhh_b[4096 + i];
    }
}

__global__ void zero_kernel() {
    int i = blockIdx.x * 256 + threadIdx.x;
    if (i < 2 * BSZ * HDIM) {
        (&g_h0[0][0])[i] = 0.f;
        (&g_c0[0][0])[i] = 0.f;
        (&g_h1[0][0])[i] = 0.f;
        (&g_c1[0][0])[i] = 0.f;
    }
}

extern "C" void kernel_launch(void* const* d_in, const int* in_sizes, int n_in,
                              void* d_out, int out_size) {
    const float* x     = (const float*)d_in[0];
    const float* Wih_f = (const float*)d_in[1];
    const float* Whh_f = (const float*)d_in[2];
    const float* bih_f = (const float*)d_in[3];
    const float* bhh_f = (const float*)d_in[4];
    const float* Wih_b = (const float*)d_in[5];
    const float* Whh_b = (const float*)d_in[6];
    const float* bih_b = (const float*)d_in[7];
    const float* bhh_b = (const float*)d_in[8];
    float* out = (float*)d_out;

    static bool attr_set = false;
    if (!attr_set) {
        cudaFuncSetAttribute(scan_kernel, cudaFuncAttributeMaxDynamicSharedMemorySize, SMEM_BYTES);
        attr_set = true;
    }

    bsum_kernel<<<16, 256>>>(bih_f, bhh_f, bih_b, bhh_b);
    zero_kernel<<<512, 256>>>();
    pack_kernel<<<24576, 256>>>(Whh_f, Whh_b, Wih_f, Wih_b);
    g0_kernel<<<65536, 256>>>(x, Wih_f, Wih_b);
    scan_kernel<<<NBLK, 256, SMEM_BYTES>>>(out);
}

// round 6
// speedup vs baseline: 1.7241x; 1.0354x over previous
#include <cuda_runtime.h>
#include <cstdint>

#define HDIM 1024
#define BSZ 64
#define TLEN 512
#define G4 4096
#define KC 32
#define LDS 36
#define NBLK 128
#define NTHR 512
#define STAGES 4
#define STGF (64 * LDS)          // 2304 floats per matrix per stage
// [2 groups][4 stages] x {A,W} + G0 tile
#define SMEM_FLOATS (2 * 2 * STAGES * STGF + 4096)
#define SMEM_BYTES (SMEM_FLOATS * 4)

// scratch (device statics; no allocations)
__device__ float g_G0[268435456];          // [T][dir][B][4096] precomputed x-gates (+bias), 1 GiB
__device__ float g_Wp1[33554432];          // packed phase1 weights [dir][nb][64][1024]
__device__ float g_Wp2[67108864];          // packed phase2 weights [dir][nb][64][2048]
__device__ float g_bsum[4][G4];            // bias sums: f0, b0, f1, b1
__device__ float g_h0[2][BSZ * HDIM];      // layer0 carried h (backward), ping-pong (tf32-rounded)
__device__ float g_c0[2][BSZ * HDIM];
__device__ float g_h1[2][BSZ * HDIM];      // layer1 carried h (backward), ping-pong (tf32-rounded)
__device__ float g_c1[2][BSZ * HDIM];
__device__ float g_hf0[2][BSZ * HDIM];     // layer0 forward h, ping-pong
__device__ unsigned g_gen;
__device__ unsigned g_cnt;

__device__ __forceinline__ float f2tf32(float x) {
    unsigned u;
    asm("cvt.rna.tf32.f32 %0, %1;" : "=r"(u) : "f"(x));
    return __uint_as_float(u);
}

__device__ __forceinline__ void mma8(float acc[4], const float a[4], const float b[2]) {
    const unsigned* A = reinterpret_cast<const unsigned*>(a);
    const unsigned* B = reinterpret_cast<const unsigned*>(b);
    asm volatile(
        "mma.sync.aligned.m16n8k8.row.col.f32.tf32.tf32.f32 "
        "{%0,%1,%2,%3}, {%4,%5,%6,%7}, {%8,%9}, {%0,%1,%2,%3};\n"
        : "+f"(acc[0]), "+f"(acc[1]), "+f"(acc[2]), "+f"(acc[3])
        : "r"(A[0]), "r"(A[1]), "r"(A[2]), "r"(A[3]), "r"(B[0]), "r"(B[1]));
}

// fast, overflow-safe activations
__device__ __forceinline__ float sigf(float x) {
    return __fdividef(1.0f, 1.0f + __expf(-x));
}
__device__ __forceinline__ float tanh_(float x) {
    float a = fabsf(x);
    float e = __expf(-2.0f * a);
    float r = __fdividef(1.0f - e, 1.0f + e);
    return copysignf(r, x);
}

__device__ __forceinline__ uint64_t mkpol_last() {
    uint64_t p;
    asm("createpolicy.fractional.L2::evict_last.b64 %0, 1.0;" : "=l"(p));
    return p;
}
__device__ __forceinline__ uint64_t mkpol_first() {
    uint64_t p;
    asm("createpolicy.fractional.L2::evict_first.b64 %0, 1.0;" : "=l"(p));
    return p;
}
__device__ __forceinline__ void cp16(void* dst, const void* src) {
    unsigned d = (unsigned)__cvta_generic_to_shared(dst);
    asm volatile("cp.async.cg.shared.global [%0], [%1], 16;" :: "r"(d), "l"(src));
}
__device__ __forceinline__ void cp16p(void* dst, const void* src, uint64_t pol) {
    unsigned d = (unsigned)__cvta_generic_to_shared(dst);
    asm volatile("cp.async.cg.shared.global.L2::cache_hint [%0], [%1], 16, %2;"
                 :: "r"(d), "l"(src), "l"(pol));
}
#define CP_COMMIT() asm volatile("cp.async.commit_group;")
#define CP_WAIT(n)  asm volatile("cp.async.wait_group %0;" :: "n"(n))

__device__ __forceinline__ float4 cvt4(float4 v) {
    v.x = f2tf32(v.x); v.y = f2tf32(v.y); v.z = f2tf32(v.z); v.w = f2tf32(v.w);
    return v;
}

// Software grid barrier. Safe: 128 blocks <= 148 SMs, all co-resident.
__device__ __forceinline__ void grid_bar() {
    __syncthreads();
    if (threadIdx.x == 0) {
        volatile unsigned* vg = &g_gen;
        unsigned gen = *vg;
        __threadfence();                       // release
        if (atomicAdd(&g_cnt, 1u) == NBLK - 1) {
            g_cnt = 0;
            __threadfence();
            *vg = gen + 1;
        } else {
            while (*vg == gen) { __nanosleep(20); }
        }
        __threadfence();                       // acquire
    }
    __syncthreads();
}

// ---------------------------------------------------------------------------
// One GEMM+LSTM phase of the scan, K-split across two 8-warp groups.
// mode 1: layer0  gates = G0[t] + h_prev0 @ Whh0^T           (32 chunks: 16+16)
// mode 2: layer1  gates = h_in @ Wih1^T + h_prev1 @ Whh1^T   (64 chunks: 32+32,
//                 group0 = Wih half on A0, group1 = Whh half on A1)
// Block computes M=64 (batch) x N=64 (4 gates x 16 units).
// ---------------------------------------------------------------------------
__device__ __forceinline__ void scan_phase(
    int mode, int t, int dir, int nblk,
    float* __restrict__ dout,
    float* sA, float* sW, float* sG,
    uint64_t polL, uint64_t polF)
{
    const int tid = threadIdx.x;
    const int kw = tid >> 8;                  // K-group 0/1
    const int ltid = tid & 255;
    const int p = t & 1;
    const int n0 = nblk * 16;

    const float *Ag, *Wb;
    int nh, wstride;
    if (mode == 1) {
        Ag = g_h0[p];
        Wb = g_Wp1 + (size_t)(dir * 64 + nblk) * 64 * 1024;
        wstride = 1024;
        nh = 16;
    } else {
        Ag = kw ? g_h1[p] : (dir ? g_h0[1 - p] : g_hf0[1 - p]);
        Wb = g_Wp2 + (size_t)(dir * 64 + nblk) * 64 * 2048;
        wstride = 2048;
        nh = 32;
    }

    const int rowA0 = ltid >> 3, kq = ltid & 7, rowA1 = rowA0 + 32;

    // G0 tile prefetch (phase 1 only): its own cp.async group, issued first.
    if (mode == 1) {
        int mRow = tid >> 3, seg = (tid >> 1) & 3, half = tid & 1;
        const float* src = g_G0 + ((size_t)(2 * t + dir) * 64 + mRow) * (size_t)G4
                         + seg * HDIM + n0 + half * 8;
        float* dst = sG + mRow * 64 + seg * 16 + half * 8;
        cp16p(dst, src, polF); cp16p(dst + 4, src + 4, polF);
        CP_COMMIT();
    }

    float* sAg = sA + kw * STAGES * STGF;
    float* sWg = sW + kw * STAGES * STGF;

    auto issue = [&](int c, int buf) {
        if (c < nh) {
            int gc = kw * nh + c;                       // global chunk
            int klA = ((mode == 1) ? gc : c) * KC + kq * 4;
            int klW = gc * KC + kq * 4;
            float* dA = sAg + buf * STGF;
            float* dW = sWg + buf * STGF;
            cp16(dA + rowA0 * LDS + kq * 4, Ag + (size_t)rowA0 * HDIM + klA);
            cp16(dA + rowA1 * LDS + kq * 4, Ag + (size_t)rowA1 * HDIM + klA);
            cp16p(dW + rowA0 * LDS + kq * 4, Wb + (size_t)rowA0 * wstride + klW, polL);
            cp16p(dW + rowA1 * LDS + kq * 4, Wb + (size_t)rowA1 * wstride + klW, polL);
        }
        CP_COMMIT();
    };

    const int wid8 = (tid >> 5) & 7, lane = tid & 31;
    const int wm = wid8 & 3, wn = wid8 >> 2;    // warp tile: 16 rows x 32 cols
    const int gq = lane >> 2, tig = lane & 3;

    float acc[4][4];
    #pragma unroll
    for (int i = 0; i < 4; i++)
        #pragma unroll
        for (int j = 0; j < 4; j++) acc[i][j] = 0.f;

    #pragma unroll
    for (int s = 0; s < STAGES - 1; s++) issue(s, s);

    for (int c = 0; c < nh; c++) {
        CP_WAIT(STAGES - 2);
        __syncthreads();
        issue(c + STAGES - 1, (c + STAGES - 1) & (STAGES - 1));
        int buf = c & (STAGES - 1);
        const float* aB = sAg + buf * STGF + (wm * 16 + gq) * LDS;
        const float* wB = sWg + buf * STGF;
        #pragma unroll
        for (int k8 = 0; k8 < 4; k8++) {
            int kk = k8 * 8;
            float af[4];
            af[0] = aB[kk + tig];
            af[1] = aB[8 * LDS + kk + tig];
            af[2] = aB[kk + tig + 4];
            af[3] = aB[8 * LDS + kk + tig + 4];
            #pragma unroll
            for (int nt = 0; nt < 4; nt++) {
                int nl = wn * 32 + nt * 8 + gq;
                float bf[2];
                bf[0] = wB[nl * LDS + kk + tig];
                bf[1] = wB[nl * LDS + kk + tig + 4];
                mma8(acc[nt], af, bf);
            }
        }
    }
    CP_WAIT(0);
    __syncthreads();

    // combine the two K-groups' partials via smem gather
    float* gsm = sA;   // reuse group-0 stage area as 64 x 65
    {
        int r0 = wm * 16 + gq;
        if (kw == 0) {
            #pragma unroll
            for (int nt = 0; nt < 4; nt++) {
                int cc = wn * 32 + nt * 8 + tig * 2;
                gsm[r0 * 65 + cc] = acc[nt][0];
                gsm[r0 * 65 + cc + 1] = acc[nt][1];
                gsm[(r0 + 8) * 65 + cc] = acc[nt][2];
                gsm[(r0 + 8) * 65 + cc + 1] = acc[nt][3];
            }
        }
        __syncthreads();
        if (kw == 1) {
            #pragma unroll
            for (int nt = 0; nt < 4; nt++) {
                int cc = wn * 32 + nt * 8 + tig * 2;
                gsm[r0 * 65 + cc] += acc[nt][0];
                gsm[r0 * 65 + cc + 1] += acc[nt][1];
                gsm[(r0 + 8) * 65 + cc] += acc[nt][2];
                gsm[(r0 + 8) * 65 + cc + 1] += acc[nt][3];
            }
        }
    }
    __syncthreads();

    #pragma unroll
    for (int r = 0; r < 2; r++) {
        int idx = tid + NTHR * r;
        int m = idx >> 4, j = idx & 15;
        float gi = gsm[m * 65 + j];
        float gf = gsm[m * 65 + 16 + j];
        float gg = gsm[m * 65 + 32 + j];
        float go = gsm[m * 65 + 48 + j];
        int n = n0 + j;
        int hi = m * HDIM + n;
        if (mode == 1) {
            gi += sG[m * 64 + j];
            gf += sG[m * 64 + 16 + j];
            gg += sG[m * 64 + 32 + j];
            go += sG[m * 64 + 48 + j];
            float cp = g_c0[p][hi];
            float c2 = sigf(gf) * cp + sigf(gi) * tanh_(gg);
            float h2 = sigf(go) * tanh_(c2);
            if (dir == 0) {
                g_hf0[1 - p][hi] = f2tf32(h2);
            } else {
                g_h0[1 - p][hi] = f2tf32(h2);
                g_c0[1 - p][hi] = c2;
            }
        } else {
            gi += g_bsum[2 + dir][n];
            gf += g_bsum[2 + dir][HDIM + n];
            gg += g_bsum[2 + dir][2 * HDIM + n];
            go += g_bsum[2 + dir][3 * HDIM + n];
            float cp = g_c1[p][hi];
            float c2 = sigf(gf) * cp + sigf(gi) * tanh_(gg);
            float h2 = sigf(go) * tanh_(c2);
            size_t ob = ((size_t)m * TLEN + t) * 2048 + (size_t)dir * HDIM + n;
            __stcs(&dout[ob], h2);                           // out
            __stcs(&dout[67108864 + ob], c2);                // c_out
            if (t == TLEN - 1) {
                size_t lb = (size_t)m * 2048 + (size_t)dir * HDIM + n;
                dout[134217728 + lb] = h2;                   // out[:, -1]
                dout[134217728 + 131072 + lb] = c2;          // c_out[:, -1]
            }
            if (dir == 1) {
                g_h1[1 - p][hi] = f2tf32(h2);
                g_c1[1 - p][hi] = c2;
            }
        }
    }
    __syncthreads();   // protect smem before next phase's prologue
}

// Persistent scan kernel: entire 512-step recurrence in ONE launch.
__global__ __launch_bounds__(NTHR, 1) void scan_kernel(float* __restrict__ dout)
{
    extern __shared__ float smem[];
    float* sA = smem;
    float* sW = smem + 2 * STAGES * STGF;
    float* sG = smem + 4 * STAGES * STGF;

    const int bx = blockIdx.x;
    const int dir = bx >> 6;
    const int nblk = bx & 63;
    const uint64_t polL = mkpol_last();
    const uint64_t polF = mkpol_first();

    for (int t = 0; t < TLEN; t++) {
        scan_phase(1, t, dir, nblk, dout, sA, sW, sG, polL, polF);
        grid_bar();
        scan_phase(2, t, dir, nblk, dout, sA, sW, sG, polL, polF);
        // phase1(t+1) touches only parity buffers in-flight phase2(t) never
        // reads; the t+1 barrier fences everything else.
    }
}

// Repack the 6 scan weight matrices into per-block-contiguous strips.
__global__ void pack_kernel(
    const float* __restrict__ Whh_f, const float* __restrict__ Whh_b,
    const float* __restrict__ Wih_f, const float* __restrict__ Wih_b)
{
    int id = blockIdx.x * 256 + threadIdx.x;     // one float4 each
    if (id < 2097152) {                          // g_Wp1: 2 * 2^20 float4
        int dir = id >> 20;
        int r2 = id & 1048575;
        int nb = r2 >> 14;
        int r3 = r2 & 16383;
        int row = r3 >> 8;
        int kq = r3 & 255;
        int grow = (row >> 4) * 1024 + nb * 16 + (row & 15);
        const float* src = (dir ? Whh_b : Whh_f) + (size_t)grow * 1024 + kq * 4;
        float4 v = __ldcs((const float4*)src);
        *(float4*)(g_Wp1 + (size_t)id * 4) = v;
    } else {
        int id2 = id - 2097152;                  // g_Wp2: 2 * 2^21 float4
        if (id2 >= 4194304) return;
        int dir = id2 >> 21;
        int r2 = id2 & 2097151;
        int nb = r2 >> 15;
        int r3 = r2 & 32767;
        int row = r3 >> 9;
        int kq = r3 & 511;
        int k = kq * 4;
        int grow = (row >> 4) * 1024 + nb * 16 + (row & 15);
        const float* base = (k < 1024) ? ((dir ? Wih_b : Wih_f) + 4194304)
                                       : ((dir ? Whh_b : Whh_f) + 4194304);
        const float* src = base + (size_t)grow * 1024 + (k & 1023);
        float4 v = __ldcs((const float4*)src);
        *(float4*)(g_Wp2 + (size_t)id2 * 4) = v;
    }
}

// Precompute G0 = x @ Wih0^T (+ bias sums), both directions.
__global__ __launch_bounds__(256) void g0_kernel(
    const float* __restrict__ x,
    const float* __restrict__ Wih_f, const float* __restrict__ Wih_b)
{
    __shared__ float sA[2][64 * LDS];
    __shared__ float sW[2][64 * LDS];

    const int tid = threadIdx.x;
    const int bx = blockIdx.x;
    const int mtile = bx >> 7;
    const int ntile = bx & 127;
    const int dir = ntile >> 6;
    const bool revA = (dir == 1);
    const float* Ap = x + (size_t)mtile * 64 * HDIM;
    const float* Wp = dir ? Wih_b : Wih_f;
    const int wrowbase = (ntile & 63) * 64;

    const int rowA0 = tid >> 3, kq = tid & 7, rowA1 = rowA0 + 32;
    const int wr0 = wrowbase + rowA0;
    const int wr1 = wrowbase + rowA1;

    float4 ra0, ra1, rw0, rw1;
    auto do_load = [&](int kc) {
        int kl = kc * KC + kq * 4;
        if (!revA) {
            ra0 = *(const float4*)(Ap + (size_t)rowA0 * HDIM + kl);
            ra1 = *(const float4*)(Ap + (size_t)rowA1 * HDIM + kl);
        } else {
            ra0 = *(const float4*)(Ap + (size_t)rowA0 * HDIM + (HDIM - 4) - kl);
            ra1 = *(const float4*)(Ap + (size_t)rowA1 * HDIM + (HDIM - 4) - kl);
        }
        rw0 = *(const float4*)(Wp + (size_t)wr0 * HDIM + kl);
        rw1 = *(const float4*)(Wp + (size_t)wr1 * HDIM + kl);
    };
    auto rev4 = [](float4 v) { float4 r; r.x = v.w; r.y = v.z; r.z = v.y; r.w = v.x; return r; };
    auto do_store = [&](int buf) {
        float4 a0 = cvt4(ra0), a1 = cvt4(ra1);
        if (revA) { a0 = rev4(a0); a1 = rev4(a1); }
        *(float4*)(&sA[buf][rowA0 * LDS + kq * 4]) = a0;
        *(float4*)(&sA[buf][rowA1 * LDS + kq * 4]) = a1;
        *(float4*)(&sW[buf][rowA0 * LDS + kq * 4]) = cvt4(rw0);
        *(float4*)(&sW[buf][rowA1 * LDS + kq * 4]) = cvt4(rw1);
    };

    const int wid = tid >> 5, lane = tid & 31;
    const int wm = wid & 3, wn = wid >> 2;
    const int gq = lane >> 2, tig = lane & 3;

    float acc[4][4];
    #pragma unroll
    for (int i = 0; i < 4; i++)
        #pragma unroll
        for (int j = 0; j < 4; j++) acc[i][j] = 0.f;

    do_load(0);
    do_store(0);
    __syncthreads();

    for (int kc = 0; kc < 32; kc++) {
        int buf = kc & 1;
        if (kc + 1 < 32) do_load(kc + 1);
        const float* aB = &sA[buf][(wm * 16 + gq) * LDS];
        #pragma unroll
        for (int k8 = 0; k8 < 4; k8++) {
            int kk = k8 * 8;
            float af[4];
            af[0] = aB[kk + tig];
            af[1] = aB[8 * LDS + kk + tig];
            af[2] = aB[kk + tig + 4];
            af[3] = aB[8 * LDS + kk + tig + 4];
            #pragma unroll
            for (int nt = 0; nt < 4; nt++) {
                int nl = wn * 32 + nt * 8 + gq;
                float bf[2];
                bf[0] = sW[buf][nl * LDS + kk + tig];
                bf[1] = sW[buf][nl * LDS + kk + tig + 4];
                mma8(acc[nt], af, bf);
            }
        }
        if (kc + 1 < 32) do_store(buf ^ 1);
        __syncthreads();
    }

    // scatter D + bias directly to g_G0 ([T][dir][B][4096]), streaming stores
    int b = mtile >> 3, tb = (mtile & 7) * 64;
    int ncd = (ntile & 63) * 64 + wn * 32;
    int r0 = wm * 16 + gq;
    #pragma unroll
    for (int nt = 0; nt < 4; nt++) {
        int cc = ncd + nt * 8 + tig * 2;
        float bs0 = g_bsum[dir][cc], bs1 = g_bsum[dir][cc + 1];
        size_t d0 = ((size_t)((tb + r0) * 2 + dir) * 64 + b) * (size_t)G4 + cc;
        size_t d2 = ((size_t)((tb + r0 + 8) * 2 + dir) * 64 + b) * (size_t)G4 + cc;
        __stcs(&g_G0[d0], acc[nt][0] + bs0);
        __stcs(&g_G0[d0 + 1], acc[nt][1] + bs1);
        __stcs(&g_G0[d2], acc[nt][2] + bs0);
        __stcs(&g_G0[d2 + 1], acc[nt][3] + bs1);
    }
}

__global__ void bsum_kernel(const float* __restrict__ bih_f, const float* __restrict__ bhh_f,
                            const float* __restrict__ bih_b, const float* __restrict__ bhh_b) {
    int i = blockIdx.x * 256 + threadIdx.x;
    if (i < 4096) {
        g_bsum[0][i] = bih_f[i] + bhh_f[i];
        g_bsum[2][i] = bih_f[4096 + i] + bhh_f[4096 + i];
        g_bsum[1][i] = bih_b[i] + bhh_b[i];
        g_bsum[3][i] = bih_b[4096 + i] + bhh_b[4096 + i];
    }
}

__global__ void zero_kernel() {
    int i = blockIdx.x * 256 + threadIdx.x;
    if (i < 2 * BSZ * HDIM) {
        (&g_h0[0][0])[i] = 0.f;
        (&g_c0[0][0])[i] = 0.f;
        (&g_h1[0][0])[i] = 0.f;
        (&g_c1[0][0])[i] = 0.f;
    }
}

extern "C" void kernel_launch(void* const* d_in, const int* in_sizes, int n_in,
                              void* d_out, int out_size) {
    const float* x     = (const float*)d_in[0];
    const float* Wih_f = (const float*)d_in[1];
    const float* Whh_f = (const float*)d_in[2];
    const float* bih_f = (const float*)d_in[3];
    const float* bhh_f = (const float*)d_in[4];
    const float* Wih_b = (const float*)d_in[5];
    const float* Whh_b = (const float*)d_in[6];
    const float* bih_b = (const float*)d_in[7];
    const float* bhh_b = (const float*)d_in[8];
    float* out = (float*)d_out;

    static bool attr_set = false;
    if (!attr_set) {
        cudaFuncSetAttribute(scan_kernel, cudaFuncAttributeMaxDynamicSharedMemorySize, SMEM_BYTES);
        attr_set = true;
    }

    bsum_kernel<<<16, 256>>>(bih_f, bhh_f, bih_b, bhh_b);
    zero_kernel<<<512, 256>>>();
    pack_kernel<<<24576, 256>>>(Whh_f, Whh_b, Wih_f, Wih_b);
    g0_kernel<<<65536, 256>>>(x, Wih_f, Wih_b);
    scan_kernel<<<NBLK, NTHR, SMEM_BYTES>>>(out);
}

// round 8
// speedup vs baseline: 1.9804x; 1.1487x over previous
#include <cuda_runtime.h>
#include <cstdint>

#define HDIM 1024
#define BSZ 64
#define TLEN 512
#define G4 4096
#define KC 32
#define LDS 36
#define NBLK 128
#define NTHR 512
#define STAGES 4
#define STG_A 2304               // 64 x 36 padded A stage
#define STG_W 2048               // fragment-ordered W stage (64x32 chunk)
#define STGT (STG_A + STG_W)     // 4352 floats per stage
#define SMEM_FLOATS (2 * STAGES * STGT + 4096)
#define SMEM_BYTES (SMEM_FLOATS * 4)

// scratch (device statics; no allocations)
__device__ float g_G0[268435456];          // [T][dir][B][4096] precomputed x-gates (+bias), 1 GiB
__device__ float g_Wp1[33554432];          // packed phase1 W, fragment order [dir][nb][c:32][2048]
__device__ float g_Wp2[67108864];          // packed phase2 W, fragment order [dir][nb][c:64][2048]
__device__ float g_bsum[4][G4];            // bias sums: f0, b0, f1, b1
__device__ float g_h0[2][BSZ * HDIM];      // layer0 carried h (backward), ping-pong (tf32-rounded)
__device__ float g_c0[2][BSZ * HDIM];
__device__ float g_h1[2][BSZ * HDIM];      // layer1 carried h (backward), ping-pong
__device__ float g_c1[2][BSZ * HDIM];
__device__ float g_hf0[2][BSZ * HDIM];     // layer0 forward h, ping-pong
__device__ unsigned g_gen;
__device__ unsigned g_cnt;

__device__ __forceinline__ float f2tf32(float x) {
    unsigned u;
    asm("cvt.rna.tf32.f32 %0, %1;" : "=r"(u) : "f"(x));
    return __uint_as_float(u);
}

__device__ __forceinline__ void mma8(float acc[4], const float a[4], const float b0, const float b1) {
    const unsigned* A = reinterpret_cast<const unsigned*>(a);
    asm volatile(
        "mma.sync.aligned.m16n8k8.row.col.f32.tf32.tf32.f32 "
        "{%0,%1,%2,%3}, {%4,%5,%6,%7}, {%8,%9}, {%0,%1,%2,%3};\n"
        : "+f"(acc[0]), "+f"(acc[1]), "+f"(acc[2]), "+f"(acc[3])
        : "r"(A[0]), "r"(A[1]), "r"(A[2]), "r"(A[3]),
          "r"(__float_as_uint(b0)), "r"(__float_as_uint(b1)));
}

// fast, overflow-safe activations
__device__ __forceinline__ float sigf(float x) {
    return __fdividef(1.0f, 1.0f + __expf(-x));
}
__device__ __forceinline__ float tanh_(float x) {
    float a = fabsf(x);
    float e = __expf(-2.0f * a);
    float r = __fdividef(1.0f - e, 1.0f + e);
    return copysignf(r, x);
}

__device__ __forceinline__ uint64_t mkpol_last() {
    uint64_t p;
    asm("createpolicy.fractional.L2::evict_last.b64 %0, 1.0;" : "=l"(p));
    return p;
}
__device__ __forceinline__ uint64_t mkpol_first() {
    uint64_t p;
    asm("createpolicy.fractional.L2::evict_first.b64 %0, 1.0;" : "=l"(p));
    return p;
}
__device__ __forceinline__ void cp16(void* dst, const void* src) {
    unsigned d = (unsigned)__cvta_generic_to_shared(dst);
    asm volatile("cp.async.cg.shared.global [%0], [%1], 16;" :: "r"(d), "l"(src));
}
__device__ __forceinline__ void cp16p(void* dst, const void* src, uint64_t pol) {
    unsigned d = (unsigned)__cvta_generic_to_shared(dst);
    asm volatile("cp.async.cg.shared.global.L2::cache_hint [%0], [%1], 16, %2;"
                 :: "r"(d), "l"(src), "l"(pol));
}
#define CP_COMMIT() asm volatile("cp.async.commit_group;")
#define CP_WAIT(n)  asm volatile("cp.async.wait_group %0;" :: "n"(n))

__device__ __forceinline__ float4 cvt4(float4 v) {
    v.x = f2tf32(v.x); v.y = f2tf32(v.y); v.z = f2tf32(v.z); v.w = f2tf32(v.w);
    return v;
}

// per-K-group barrier (256 threads each)
__device__ __forceinline__ void group_bar(int kw) {
    if (kw == 0) asm volatile("bar.sync 1, 256;" ::: "memory");
    else         asm volatile("bar.sync 2, 256;" ::: "memory");
}

// Software grid barrier. 128 blocks <= 148 SMs (co-resident). Acquire/release
// on the flag only — all cross-block data reads bypass L1 (cp.async.cg/__ldcg),
// so no CCTL.IVALL (threadfence) is needed.
__device__ __forceinline__ void grid_bar() {
    __syncthreads();
    if (threadIdx.x == 0) {
        unsigned gen;
        asm volatile("ld.acquire.gpu.global.u32 %0, [%1];" : "=r"(gen) : "l"(&g_gen));
        unsigned arrived;
        asm volatile("atom.release.gpu.global.add.u32 %0, [%1], 1;"
                     : "=r"(arrived) : "l"(&g_cnt));
        if (arrived == NBLK - 1) {
            g_cnt = 0;
            asm volatile("st.release.gpu.global.u32 [%0], %1;" :: "l"(&g_gen), "r"(gen + 1));
        } else {
            unsigned cur;
            do {
                __nanosleep(20);
                asm volatile("ld.acquire.gpu.global.u32 %0, [%1];" : "=r"(cur) : "l"(&g_gen));
            } while (cur == gen);
        }
    }
    __syncthreads();
}

// ---------------------------------------------------------------------------
// One GEMM+LSTM phase, K-split across two 8-warp groups.
// mode 1: layer0  gates = G0[t] + h_prev0 @ Whh0^T           (32 chunks: 16+16)
// mode 2: layer1  gates = h_in @ Wih1^T + h_prev1 @ Whh1^T   (64 chunks: 32+32)
// Block computes M=64 (batch) x N=64 (4 gates x 16 units).
// ---------------------------------------------------------------------------
__device__ __forceinline__ void scan_phase(
    int mode, int t, int dir, int nblk,
    float* __restrict__ dout,
    float* smem, float* sG,
    uint64_t polL, uint64_t polF)
{
    const int tid = threadIdx.x;
    const int kw = tid >> 8;                  // K-group 0/1
    const int ltid = tid & 255;
    const int p = t & 1;
    const int n0 = nblk * 16;

    const float *Ag, *Wb;
    int nh;
    if (mode == 1) {
        Ag = g_h0[p];
        Wb = g_Wp1 + (size_t)(dir * 64 + nblk) * 32 * 2048;
        nh = 16;
    } else {
        Ag = kw ? g_h1[p] : (dir ? g_h0[1 - p] : g_hf0[1 - p]);
        Wb = g_Wp2 + (size_t)(dir * 64 + nblk) * 64 * 2048;
        nh = 32;
    }

    const int rowA0 = ltid >> 3, kq = ltid & 7, rowA1 = rowA0 + 32;
    float* sBase = smem + kw * STAGES * STGT;

    auto prefetch_g0 = [&](int tt) {
        int mRow = tid >> 3, seg = (tid >> 1) & 3, half = tid & 1;
        const float* src = g_G0 + ((size_t)(2 * tt + dir) * 64 + mRow) * (size_t)G4
                         + seg * HDIM + n0 + half * 8;
        float* dst = sG + mRow * 64 + seg * 16 + half * 8;
        cp16p(dst, src, polF); cp16p(dst + 4, src + 4, polF);
    };

    auto issue = [&](int c, int buf) {
        if (c < nh) {
            int gc = kw * nh + c;                       // global chunk
            int klA = ((mode == 1) ? gc : c) * KC + kq * 4;
            float* dA = sBase + buf * STGT;
            float* dW = dA + STG_A;
            const float* wsrc = Wb + (size_t)gc * 2048;
            cp16(dA + rowA0 * LDS + kq * 4, Ag + (size_t)rowA0 * HDIM + klA);
            cp16(dA + rowA1 * LDS + kq * 4, Ag + (size_t)rowA1 * HDIM + klA);
            cp16p(dW + ltid * 4, wsrc + ltid * 4, polL);
            cp16p(dW + (ltid + 256) * 4, wsrc + (ltid + 256) * 4, polL);
        }
        // inject next step's G0 prefetch into a mid-phase2 group (fully hidden)
        if (mode == 2 && c == 16 && t + 1 < TLEN) prefetch_g0(t + 1);
        CP_COMMIT();
    };

    const int wid8 = (tid >> 5) & 7, lane = tid & 31;
    const int wm = wid8 & 3, wn = wid8 >> 2;    // warp tile: 16 rows x 32 cols
    const int gq = lane >> 2, tig = lane & 3;

    float acc[4][4];
    #pragma unroll
    for (int i = 0; i < 4; i++)
        #pragma unroll
        for (int j = 0; j < 4; j++) acc[i][j] = 0.f;

    #pragma unroll
    for (int s = 0; s < STAGES - 1; s++) issue(s, s);

    for (int c = 0; c < nh; c++) {
        CP_WAIT(STAGES - 2);
        group_bar(kw);
        issue(c + STAGES - 1, (c + STAGES - 1) & (STAGES - 1));
        int buf = c & (STAGES - 1);
        const float* aB = sBase + buf * STGT + (wm * 16 + gq) * LDS;
        const float2* wF = (const float2*)(sBase + buf * STGT + STG_A);
        #pragma unroll
        for (int k8 = 0; k8 < 4; k8++) {
            int kk = k8 * 8;
            float af[4];
            af[0] = aB[kk + tig];
            af[1] = aB[8 * LDS + kk + tig];
            af[2] = aB[kk + tig + 4];
            af[3] = aB[8 * LDS + kk + tig + 4];
            #pragma unroll
            for (int nt = 0; nt < 4; nt++) {
                float2 bv = wF[((k8 * 2 + wn) * 4 + nt) * 32 + lane];
                mma8(acc[nt], af, bv.x, bv.y);
            }
        }
    }
    CP_WAIT(0);
    __syncthreads();

    // combine the two K-groups' partials via smem gather
    float* gsm = smem;   // reuse group-0 stage area as 64 x 65
    {
        int r0 = wm * 16 + gq;
        if (kw == 0) {
            #pragma unroll
            for (int nt = 0; nt < 4; nt++) {
                int cc = wn * 32 + nt * 8 + tig * 2;
                gsm[r0 * 65 + cc] = acc[nt][0];
                gsm[r0 * 65 + cc + 1] = acc[nt][1];
                gsm[(r0 + 8) * 65 + cc] = acc[nt][2];
                gsm[(r0 + 8) * 65 + cc + 1] = acc[nt][3];
            }
        }
        __syncthreads();
        if (kw == 1) {
            #pragma unroll
            for (int nt = 0; nt < 4; nt++) {
                int cc = wn * 32 + nt * 8 + tig * 2;
                gsm[r0 * 65 + cc] += acc[nt][0];
                gsm[r0 * 65 + cc + 1] += acc[nt][1];
                gsm[(r0 + 8) * 65 + cc] += acc[nt][2];
                gsm[(r0 + 8) * 65 + cc + 1] += acc[nt][3];
            }
        }
    }
    __syncthreads();

    #pragma unroll
    for (int r = 0; r < 2; r++) {
        int idx = tid + NTHR * r;
        int m = idx >> 4, j = idx & 15;
        float gi = gsm[m * 65 + j];
        float gf = gsm[m * 65 + 16 + j];
        float gg = gsm[m * 65 + 32 + j];
        float go = gsm[m * 65 + 48 + j];
        int n = n0 + j;
        int hi = m * HDIM + n;
        if (mode == 1) {
            gi += sG[m * 64 + j];
            gf += sG[m * 64 + 16 + j];
            gg += sG[m * 64 + 32 + j];
            go += sG[m * 64 + 48 + j];
            float cp = __ldcg(&g_c0[p][hi]);
            float c2 = sigf(gf) * cp + sigf(gi) * tanh_(gg);
            float h2 = sigf(go) * tanh_(c2);
            if (dir == 0) {
                g_hf0[1 - p][hi] = f2tf32(h2);
            } else {
                g_h0[1 - p][hi] = f2tf32(h2);
                g_c0[1 - p][hi] = c2;
            }
        } else {
            gi += g_bsum[2 + dir][n];
            gf += g_bsum[2 + dir][HDIM + n];
            gg += g_bsum[2 + dir][2 * HDIM + n];
            go += g_bsum[2 + dir][3 * HDIM + n];
            float cp = __ldcg(&g_c1[p][hi]);
            float c2 = sigf(gf) * cp + sigf(gi) * tanh_(gg);
            float h2 = sigf(go) * tanh_(c2);
            size_t ob = ((size_t)m * TLEN + t) * 2048 + (size_t)dir * HDIM + n;
            __stcs(&dout[ob], h2);                           // out
            __stcs(&dout[67108864 + ob], c2);                // c_out
            if (t == TLEN - 1) {
                size_t lb = (size_t)m * 2048 + (size_t)dir * HDIM + n;
                dout[134217728 + lb] = h2;                   // out[:, -1]
                dout[134217728 + 131072 + lb] = c2;          // c_out[:, -1]
            }
            if (dir == 1) {
                g_h1[1 - p][hi] = f2tf32(h2);
                g_c1[1 - p][hi] = c2;
            }
        }
    }
    __syncthreads();   // protect smem before next phase's prologue
}

// Persistent scan kernel: entire 512-step recurrence in ONE launch.
__global__ __launch_bounds__(NTHR, 1) void scan_kernel(float* __restrict__ dout)
{
    extern __shared__ float smem[];
    float* sG = smem + 2 * STAGES * STGT;

    const int bx = blockIdx.x;
    const int dir = bx >> 6;
    const int nblk = bx & 63;
    const int n0 = nblk * 16;
    const uint64_t polL = mkpol_last();
    const uint64_t polF = mkpol_first();

    // G0(t=0) prefetch (own group; drained by phase1(0)'s CP_WAIT(0))
    {
        int tid = threadIdx.x;
        int mRow = tid >> 3, seg = (tid >> 1) & 3, half = tid & 1;
        const float* src = g_G0 + ((size_t)(0 + dir) * 64 + mRow) * (size_t)G4
                         + seg * HDIM + n0 + half * 8;
        float* dst = sG + mRow * 64 + seg * 16 + half * 8;
        cp16p(dst, src, polF); cp16p(dst + 4, src + 4, polF);
        CP_COMMIT();
    }

    for (int t = 0; t < TLEN; t++) {
        scan_phase(1, t, dir, nblk, dout, smem, sG, polL, polF);
        grid_bar();
        scan_phase(2, t, dir, nblk, dout, smem, sG, polL, polF);
        // phase1(t+1) touches only parity buffers in-flight phase2(t) never
        // reads; the t+1 barrier fences everything else.
    }
}

// Repack the 6 scan weight matrices into per-block, per-chunk, mma-fragment
// order so the GEMM's B operand loads as LDS.64 with zero rearrangement.
// Fragment float layout within a 2048-float chunk:
//   [frag = (k8*2+wn)*4+nt][lane = gq*4+tig][pair], content = W[n][k], where
//   n = wn*32+nt*8+gq (global row g*1024+nb*16+u), k = kchunk*32+k8*8+tig+4*pair.
__global__ void pack_kernel(
    const float* __restrict__ Whh_f, const float* __restrict__ Whh_b,
    const float* __restrict__ Wih_f, const float* __restrict__ Wih_b)
{
    int id = blockIdx.x * 256 + threadIdx.x;     // one dst float4 each
    const float* src;
    float* dst;
    int nb, c, f4, kloc;
    if (id < 2097152) {                          // g_Wp1: [dir][nb][32][2048]
        int dir = id >> 20;
        int r = id & 1048575;
        nb = r >> 14;
        int r2 = r & 16383;
        c = r2 >> 9;
        f4 = r2 & 511;
        src = dir ? Whh_b : Whh_f;
        kloc = c * 32;
        dst = g_Wp1 + (size_t)id * 4;
    } else {
        int id2 = id - 2097152;                  // g_Wp2: [dir][nb][64][2048]
        if (id2 >= 4194304) return;
        int dir = id2 >> 21;
        int r = id2 & 2097151;
        nb = r >> 15;
        int r2 = r & 32767;
        c = r2 >> 9;
        f4 = r2 & 511;
        src = ((c < 32) ? (dir ? Wih_b : Wih_f) : (dir ? Whh_b : Whh_f)) + 4194304;
        kloc = (c & 31) * 32;
        dst = g_Wp2 + (size_t)id2 * 4;
    }
    int frag = f4 >> 4, rem = f4 & 15;
    int k8 = frag >> 3, wn = (frag >> 2) & 1, nt = frag & 3;
    float out[4];
    #pragma unroll
    for (int j = 0; j < 4; j++) {
        int lane = rem * 2 + (j >> 1);
        int pr = j & 1;
        int gq = lane >> 2, tig = lane & 3;
        int n = wn * 32 + nt * 8 + gq;
        int grow = (n >> 4) * 1024 + nb * 16 + (n & 15);
        int k = kloc + k8 * 8 + tig + 4 * pr;
        out[j] = __ldcs(&src[(size_t)grow * 1024 + k]);
    }
    *(float4*)dst = *(float4*)out;
}

// Precompute G0 = x @ Wih0^T (+ bias sums), both directions.
__global__ __launch_bounds__(256) void g0_kernel(
    const float* __restrict__ x,
    const float* __restrict__ Wih_f, const float* __restrict__ Wih_b)
{
    __shared__ float sA[2][64 * LDS];
    __shared__ float sW[2][64 * LDS];

    const int tid = threadIdx.x;
    const int bx = blockIdx.x;
    const int mtile = bx >> 7;
    const int ntile = bx & 127;
    const int dir = ntile >> 6;
    const bool revA = (dir == 1);
    const float* Ap = x + (size_t)mtile * 64 * HDIM;
    const float* Wp = dir ? Wih_b : Wih_f;
    const int wrowbase = (ntile & 63) * 64;

    const int rowA0 = tid >> 3, kq = tid & 7, rowA1 = rowA0 + 32;
    const int wr0 = wrowbase + rowA0;
    const int wr1 = wrowbase + rowA1;

    float4 ra0, ra1, rw0, rw1;
    auto do_load = [&](int kc) {
        int kl = kc * KC + kq * 4;
        if (!revA) {
            ra0 = *(const float4*)(Ap + (size_t)rowA0 * HDIM + kl);
            ra1 = *(const float4*)(Ap + (size_t)rowA1 * HDIM + kl);
        } else {
            ra0 = *(const float4*)(Ap + (size_t)rowA0 * HDIM + (HDIM - 4) - kl);
            ra1 = *(const float4*)(Ap + (size_t)rowA1 * HDIM + (HDIM - 4) - kl);
        }
        rw0 = *(const float4*)(Wp + (size_t)wr0 * HDIM + kl);
        rw1 = *(const float4*)(Wp + (size_t)wr1 * HDIM + kl);
    };
    auto rev4 = [](float4 v) { float4 r; r.x = v.w; r.y = v.z; r.z = v.y; r.w = v.x; return r; };
    auto do_store = [&](int buf) {
        float4 a0 = cvt4(ra0), a1 = cvt4(ra1);
        if (revA) { a0 = rev4(a0); a1 = rev4(a1); }
        *(float4*)(&sA[buf][rowA0 * LDS + kq * 4]) = a0;
        *(float4*)(&sA[buf][rowA1 * LDS + kq * 4]) = a1;
        *(float4*)(&sW[buf][rowA0 * LDS + kq * 4]) = cvt4(rw0);
        *(float4*)(&sW[buf][rowA1 * LDS + kq * 4]) = cvt4(rw1);
    };

    const int wid = tid >> 5, lane = tid & 31;
    const int wm = wid & 3, wn = wid >> 2;
    const int gq = lane >> 2, tig = lane & 3;

    float acc[4][4];
    #pragma unroll
    for (int i = 0; i < 4; i++)
        #pragma unroll
        for (int j = 0; j < 4; j++) acc[i][j] = 0.f;

    do_load(0);
    do_store(0);
    __syncthreads();

    for (int kc = 0; kc < 32; kc++) {
        int buf = kc & 1;
        if (kc + 1 < 32) do_load(kc + 1);
        const float* aB = &sA[buf][(wm * 16 + gq) * LDS];
        #pragma unroll
        for (int k8 = 0; k8 < 4; k8++) {
            int kk = k8 * 8;
            float af[4];
            af[0] = aB[kk + tig];
            af[1] = aB[8 * LDS + kk + tig];
            af[2] = aB[kk + tig + 4];
            af[3] = aB[8 * LDS + kk + tig + 4];
            #pragma unroll
            for (int nt = 0; nt < 4; nt++) {
                int nl = wn * 32 + nt * 8 + gq;
                mma8(acc[nt], af, sW[buf][nl * LDS + kk + tig], sW[buf][nl * LDS + kk + tig + 4]);
            }
        }
        if (kc + 1 < 32) do_store(buf ^ 1);
        __syncthreads();
    }

    // scatter D + bias directly to g_G0 ([T][dir][B][4096]), streaming stores
    int b = mtile >> 3, tb = (mtile & 7) * 64;
    int ncd = (ntile & 63) * 64 + wn * 32;
    int r0 = wm * 16 + gq;
    #pragma unroll
    for (int nt = 0; nt < 4; nt++) {
        int cc = ncd + nt * 8 + tig * 2;
        float bs0 = g_bsum[dir][cc], bs1 = g_bsum[dir][cc + 1];
        size_t d0 = ((size_t)((tb + r0) * 2 + dir) * 64 + b) * (size_t)G4 + cc;
        size_t d2 = ((size_t)((tb + r0 + 8) * 2 + dir) * 64 + b) * (size_t)G4 + cc;
        __stcs(&g_G0[d0], acc[nt][0] + bs0);
        __stcs(&g_G0[d0 + 1], acc[nt][1] + bs1);
        __stcs(&g_G0[d2], acc[nt][2] + bs0);
        __stcs(&g_G0[d2 + 1], acc[nt][3] + bs1);
    }
}

// merged bias-sum + state-zero init (single launch)
__global__ void init_kernel(const float* __restrict__ bih_f, const float* __restrict__ bhh_f,
                            const float* __restrict__ bih_b, const float* __restrict__ bhh_b) {
    int i = blockIdx.x * 256 + threadIdx.x;
    if (i < 4096) {
        g_bsum[0][i] = bih_f[i] + bhh_f[i];
        g_bsum[2][i] = bih_f[4096 + i] + bhh_f[4096 + i];
        g_bsum[1][i] = bih_b[i] + bhh_b[i];
        g_bsum[3][i] = bih_b[4096 + i] + bhh_b[4096 + i];
    }
    if (i < 2 * BSZ * HDIM) {
        (&g_h0[0][0])[i] = 0.f;
        (&g_c0[0][0])[i] = 0.f;
        (&g_h1[0][0])[i] = 0.f;
        (&g_c1[0][0])[i] = 0.f;
    }
}

extern "C" void kernel_launch(void* const* d_in, const int* in_sizes, int n_in,
                              void* d_out, int out_size) {
    const float* x     = (const float*)d_in[0];
    const float* Wih_f = (const float*)d_in[1];
    const float* Whh_f = (const float*)d_in[2];
    const float* bih_f = (const float*)d_in[3];
    const float* bhh_f = (const float*)d_in[4];
    const float* Wih_b = (const float*)d_in[5];
    const float* Whh_b = (const float*)d_in[6];
    const float* bih_b = (const float*)d_in[7];
    const float* bhh_b = (const float*)d_in[8];
    float* out = (float*)d_out;

    static bool attr_set = false;
    if (!attr_set) {
        cudaFuncSetAttribute(scan_kernel, cudaFuncAttributeMaxDynamicSharedMemorySize, SMEM_BYTES);
        attr_set = true;
    }

    init_kernel<<<512, 256>>>(bih_f, bhh_f, bih_b, bhh_b);
    pack_kernel<<<24576, 256>>>(Whh_f, Whh_b, Wih_f, Wih_b);
    g0_kernel<<<65536, 256>>>(x, Wih_f, Wih_b);
    scan_kernel<<<NBLK, NTHR, SMEM_BYTES>>>(out);
}

// round 9
// speedup vs baseline: 2.4252x; 1.2246x over previous
#include <cuda_runtime.h>
#include <cstdint>

#define HDIM 1024
#define BSZ 64
#define TLEN 512
#define G4 4096
#define KC 32
#define LDS 36
#define NBLK 128
#define NTHR 512
#define NGRP 4
#define STAGES 3
#define STG_A 2304               // 64 x 36 padded A stage
#define STG_W 2048               // fragment-ordered W stage (64x32 chunk)
#define STGT (STG_A + STG_W)     // 4352 floats per stage
#define GSLAB 4160               // 64 x 65 partial slab per group
#define SMEM_FLOATS (NGRP * STAGES * STGT + 4096)
#define SMEM_BYTES (SMEM_FLOATS * 4)

// scratch (device statics; no allocations)
__device__ float g_G0[268435456];          // [T][dir][B][4096] precomputed x-gates (+bias), 1 GiB
__device__ float g_Wp1[33554432];          // packed phase1 W, fragment order [dir][nb][c:32][2048]
__device__ float g_Wp2[67108864];          // packed phase2 W, fragment order [dir][nb][c:64][2048]
__device__ float g_bsum[4][G4];            // bias sums: f0, b0, f1, b1
__device__ float g_h0[2][BSZ * HDIM];      // layer0 carried h (backward), ping-pong (tf32-rounded)
__device__ float g_c0[2][BSZ * HDIM];
__device__ float g_h1[2][BSZ * HDIM];      // layer1 carried h (backward), ping-pong
__device__ float g_c1[2][BSZ * HDIM];
__device__ float g_hf0[2][BSZ * HDIM];     // layer0 forward h, ping-pong
__device__ unsigned g_gen;
__device__ unsigned g_cnt;

__device__ __forceinline__ float f2tf32(float x) {
    unsigned u;
    asm("cvt.rna.tf32.f32 %0, %1;" : "=r"(u) : "f"(x));
    return __uint_as_float(u);
}

__device__ __forceinline__ void mma8(float acc[4], const float a[4], const float b0, const float b1) {
    const unsigned* A = reinterpret_cast<const unsigned*>(a);
    asm volatile(
        "mma.sync.aligned.m16n8k8.row.col.f32.tf32.tf32.f32 "
        "{%0,%1,%2,%3}, {%4,%5,%6,%7}, {%8,%9}, {%0,%1,%2,%3};\n"
        : "+f"(acc[0]), "+f"(acc[1]), "+f"(acc[2]), "+f"(acc[3])
        : "r"(A[0]), "r"(A[1]), "r"(A[2]), "r"(A[3]),
          "r"(__float_as_uint(b0)), "r"(__float_as_uint(b1)));
}

// fast, overflow-safe activations
__device__ __forceinline__ float sigf(float x) {
    return __fdividef(1.0f, 1.0f + __expf(-x));
}
__device__ __forceinline__ float tanh_(float x) {
    float a = fabsf(x);
    float e = __expf(-2.0f * a);
    float r = __fdividef(1.0f - e, 1.0f + e);
    return copysignf(r, x);
}

__device__ __forceinline__ uint64_t mkpol_last() {
    uint64_t p;
    asm("createpolicy.fractional.L2::evict_last.b64 %0, 1.0;" : "=l"(p));
    return p;
}
__device__ __forceinline__ uint64_t mkpol_first() {
    uint64_t p;
    asm("createpolicy.fractional.L2::evict_first.b64 %0, 1.0;" : "=l"(p));
    return p;
}
__device__ __forceinline__ void cp16(void* dst, const void* src) {
    unsigned d = (unsigned)__cvta_generic_to_shared(dst);
    asm volatile("cp.async.cg.shared.global [%0], [%1], 16;" :: "r"(d), "l"(src));
}
__device__ __forceinline__ void cp16p(void* dst, const void* src, uint64_t pol) {
    unsigned d = (unsigned)__cvta_generic_to_shared(dst);
    asm volatile("cp.async.cg.shared.global.L2::cache_hint [%0], [%1], 16, %2;"
                 :: "r"(d), "l"(src), "l"(pol));
}
#define CP_COMMIT() asm volatile("cp.async.commit_group;")
#define CP_WAIT(n)  asm volatile("cp.async.wait_group %0;" :: "n"(n))

__device__ __forceinline__ float4 cvt4(float4 v) {
    v.x = f2tf32(v.x); v.y = f2tf32(v.y); v.z = f2tf32(v.z); v.w = f2tf32(v.w);
    return v;
}

// per-K-group barrier (128 threads each, barrier ids 1..4)
__device__ __forceinline__ void group_bar(int kw) {
    asm volatile("bar.sync %0, 128;" :: "r"(kw + 1) : "memory");
}

// Software grid barrier. 128 blocks <= 148 SMs (co-resident). Acquire/release
// on the flag only — all cross-block data reads bypass L1 (cp.async.cg/__ldcg).
__device__ __forceinline__ void grid_bar() {
    __syncthreads();
    if (threadIdx.x == 0) {
        unsigned gen;
        asm volatile("ld.acquire.gpu.global.u32 %0, [%1];" : "=r"(gen) : "l"(&g_gen));
        unsigned arrived;
        asm volatile("atom.release.gpu.global.add.u32 %0, [%1], 1;"
                     : "=r"(arrived) : "l"(&g_cnt));
        if (arrived == NBLK - 1) {
            g_cnt = 0;
            asm volatile("st.release.gpu.global.u32 [%0], %1;" :: "l"(&g_gen), "r"(gen + 1));
        } else {
            unsigned cur;
            do {
                __nanosleep(20);
                asm volatile("ld.acquire.gpu.global.u32 %0, [%1];" : "=r"(cur) : "l"(&g_gen));
            } while (cur == gen);
        }
    }
    __syncthreads();
}

// ---------------------------------------------------------------------------
// One GEMM+LSTM phase, K-split across FOUR 4-warp groups (32x32 warp tiles).
// mode 1: layer0  gates = G0[t] + h_prev0 @ Whh0^T           (32 chunks: 8 per group)
// mode 2: layer1  gates = h_in @ Wih1^T + h_prev1 @ Whh1^T   (64 chunks: 16 per group;
//                 groups 0-1 = Wih half on h_in, groups 2-3 = Whh half on h1)
// Block computes M=64 (batch) x N=64 (4 gates x 16 units).
// ---------------------------------------------------------------------------
__device__ __forceinline__ void scan_phase(
    int mode, int t, int dir, int nblk,
    float* __restrict__ dout,
    float* smem, float* sG,
    uint64_t polL, uint64_t polF)
{
    const int tid = threadIdx.x;
    const int kw = tid >> 7;                  // K-group 0..3
    const int ltid = tid & 127;
    const int p = t & 1;
    const int n0 = nblk * 16;

    const float *Ag, *Wb;
    int nh;
    if (mode == 1) {
        Ag = g_h0[p];
        Wb = g_Wp1 + (size_t)(dir * 64 + nblk) * 32 * 2048;
        nh = 8;
    } else {
        Ag = (kw < 2) ? (dir ? g_h0[1 - p] : g_hf0[1 - p]) : g_h1[p];
        Wb = g_Wp2 + (size_t)(dir * 64 + nblk) * 64 * 2048;
        nh = 16;
    }

    float* sBase = smem + kw * (STAGES * STGT);

    auto prefetch_g0 = [&](int tt) {
        int mRow = tid >> 3, seg = (tid >> 1) & 3, half = tid & 1;
        const float* src = g_G0 + ((size_t)(2 * tt + dir) * 64 + mRow) * (size_t)G4
                         + seg * HDIM + n0 + half * 8;
        float* dst = sG + mRow * 64 + seg * 16 + half * 8;
        cp16p(dst, src, polF); cp16p(dst + 4, src + 4, polF);
    };

    auto issue = [&](int c, int buf) {
        if (c < nh) {
            int gc = kw * nh + c;                       // global chunk
            int klA = ((mode == 1) ? gc : (gc & 31)) * KC;
            float* dA = sBase + buf * STGT;
            float* dW = dA + STG_A;
            const float* wsrc = Wb + (size_t)gc * 2048;
            #pragma unroll
            for (int i = 0; i < 4; i++) {
                int f = ltid + 128 * i;
                int row = f >> 3, kq = f & 7;
                cp16(dA + row * LDS + kq * 4, Ag + (size_t)row * HDIM + klA + kq * 4);
            }
            #pragma unroll
            for (int i = 0; i < 4; i++) {
                int f4 = ltid + 128 * i;
                cp16p(dW + f4 * 4, wsrc + (size_t)f4 * 4, polL);
            }
        }
        // inject next step's G0 prefetch mid-phase2 (fully hidden)
        if (mode == 2 && c == 8 && t + 1 < TLEN) prefetch_g0(t + 1);
        CP_COMMIT();
    };

    const int wid4 = (tid >> 5) & 3, lane = tid & 31;
    const int wm = wid4 >> 1, wn = wid4 & 1;    // warp tile: 32 rows x 32 cols
    const int gq = lane >> 2, tig = lane & 3;

    float acc[2][4][4];
    #pragma unroll
    for (int mt = 0; mt < 2; mt++)
        #pragma unroll
        for (int i = 0; i < 4; i++)
            #pragma unroll
            for (int j = 0; j < 4; j++) acc[mt][i][j] = 0.f;

    issue(0, 0);
    issue(1, 1);

    int buf = 0, nb = 2;
    for (int c = 0; c < nh; c++) {
        CP_WAIT(1);
        group_bar(kw);
        issue(c + 2, nb);
        const float* aB = sBase + buf * STGT + (wm * 32 + gq) * LDS;
        const float2* wF = (const float2*)(sBase + buf * STGT + STG_A);
        #pragma unroll
        for (int k8 = 0; k8 < 4; k8++) {
            int kk = k8 * 8;
            float af0[4], af1[4];
            af0[0] = aB[kk + tig];
            af0[1] = aB[8 * LDS + kk + tig];
            af0[2] = aB[kk + tig + 4];
            af0[3] = aB[8 * LDS + kk + tig + 4];
            af1[0] = aB[16 * LDS + kk + tig];
            af1[1] = aB[24 * LDS + kk + tig];
            af1[2] = aB[16 * LDS + kk + tig + 4];
            af1[3] = aB[24 * LDS + kk + tig + 4];
            #pragma unroll
            for (int nt = 0; nt < 4; nt++) {
                float2 bv = wF[((k8 * 2 + wn) * 4 + nt) * 32 + lane];
                mma8(acc[0][nt], af0, bv.x, bv.y);
                mma8(acc[1][nt], af1, bv.x, bv.y);
            }
        }
        buf++; if (buf == STAGES) buf = 0;
        nb++;  if (nb == STAGES) nb = 0;
    }
    CP_WAIT(0);
    __syncthreads();

    // each group writes its partials to its own 64x65 slab
    {
        float* gsm = smem + kw * GSLAB;
        #pragma unroll
        for (int mt = 0; mt < 2; mt++) {
            int r0 = wm * 32 + mt * 16 + gq;
            #pragma unroll
            for (int nt = 0; nt < 4; nt++) {
                int cc = wn * 32 + nt * 8 + tig * 2;
                gsm[r0 * 65 + cc] = acc[mt][nt][0];
                gsm[r0 * 65 + cc + 1] = acc[mt][nt][1];
                gsm[(r0 + 8) * 65 + cc] = acc[mt][nt][2];
                gsm[(r0 + 8) * 65 + cc + 1] = acc[mt][nt][3];
            }
        }
    }
    __syncthreads();

    #pragma unroll
    for (int r = 0; r < 2; r++) {
        int idx = tid + NTHR * r;
        int m = idx >> 4, j = idx & 15;
        int base = m * 65 + j;
        float gi = 0.f, gf = 0.f, gg = 0.f, go = 0.f;
        #pragma unroll
        for (int g = 0; g < NGRP; g++) {
            const float* gs = smem + g * GSLAB;
            gi += gs[base];
            gf += gs[base + 16];
            gg += gs[base + 32];
            go += gs[base + 48];
        }
        int n = n0 + j;
        int hi = m * HDIM + n;
        if (mode == 1) {
            gi += sG[m * 64 + j];
            gf += sG[m * 64 + 16 + j];
            gg += sG[m * 64 + 32 + j];
            go += sG[m * 64 + 48 + j];
            float cp = __ldcg(&g_c0[p][hi]);
            float c2 = sigf(gf) * cp + sigf(gi) * tanh_(gg);
            float h2 = sigf(go) * tanh_(c2);
            if (dir == 0) {
                g_hf0[1 - p][hi] = f2tf32(h2);
            } else {
                g_h0[1 - p][hi] = f2tf32(h2);
                g_c0[1 - p][hi] = c2;
            }
        } else {
            gi += g_bsum[2 + dir][n];
            gf += g_bsum[2 + dir][HDIM + n];
            gg += g_bsum[2 + dir][2 * HDIM + n];
            go += g_bsum[2 + dir][3 * HDIM + n];
            float cp = __ldcg(&g_c1[p][hi]);
            float c2 = sigf(gf) * cp + sigf(gi) * tanh_(gg);
            float h2 = sigf(go) * tanh_(c2);
            size_t ob = ((size_t)m * TLEN + t) * 2048 + (size_t)dir * HDIM + n;
            __stcs(&dout[ob], h2);                           // out
            __stcs(&dout[67108864 + ob], c2);                // c_out
            if (t == TLEN - 1) {
                size_t lb = (size_t)m * 2048 + (size_t)dir * HDIM + n;
                dout[134217728 + lb] = h2;                   // out[:, -1]
                dout[134217728 + 131072 + lb] = c2;          // c_out[:, -1]
            }
            if (dir == 1) {
                g_h1[1 - p][hi] = f2tf32(h2);
                g_c1[1 - p][hi] = c2;
            }
        }
    }
    __syncthreads();   // protect smem before next phase's prologue
}

// Persistent scan kernel: entire 512-step recurrence in ONE launch.
__global__ __launch_bounds__(NTHR, 1) void scan_kernel(float* __restrict__ dout)
{
    extern __shared__ float smem[];
    float* sG = smem + NGRP * STAGES * STGT;

    const int bx = blockIdx.x;
    const int dir = bx >> 6;
    const int nblk = bx & 63;
    const int n0 = nblk * 16;
    const uint64_t polL = mkpol_last();
    const uint64_t polF = mkpol_first();

    // G0(t=0) prefetch (own group; drained by phase1(0)'s waits)
    {
        int tid = threadIdx.x;
        int mRow = tid >> 3, seg = (tid >> 1) & 3, half = tid & 1;
        const float* src = g_G0 + ((size_t)(0 + dir) * 64 + mRow) * (size_t)G4
                         + seg * HDIM + n0 + half * 8;
        float* dst = sG + mRow * 64 + seg * 16 + half * 8;
        cp16p(dst, src, polF); cp16p(dst + 4, src + 4, polF);
        CP_COMMIT();
    }

    for (int t = 0; t < TLEN; t++) {
        scan_phase(1, t, dir, nblk, dout, smem, sG, polL, polF);
        grid_bar();
        scan_phase(2, t, dir, nblk, dout, smem, sG, polL, polF);
        // phase1(t+1) touches only parity buffers in-flight phase2(t) never
        // reads; the t+1 barrier fences everything else.
    }
}

// Repack the 6 scan weight matrices into per-block, per-chunk, mma-fragment
// order so the GEMM's B operand loads as LDS.64 with zero rearrangement.
// Fragment float layout within a 2048-float chunk:
//   [frag = (k8*2+wn)*4+nt][lane = gq*4+tig][pair], content = W[n][k], where
//   n = wn*32+nt*8+gq (global row g*1024+nb*16+u), k = kchunk*32+k8*8+tig+4*pair.
__global__ void pack_kernel(
    const float* __restrict__ Whh_f, const float* __restrict__ Whh_b,
    const float* __restrict__ Wih_f, const float* __restrict__ Wih_b)
{
    int id = blockIdx.x * 256 + threadIdx.x;     // one dst float4 each
    const float* src;
    float* dst;
    int nb, c, f4, kloc;
    if (id < 2097152) {                          // g_Wp1: [dir][nb][32][2048]
        int dir = id >> 20;
        int r = id & 1048575;
        nb = r >> 14;
        int r2 = r & 16383;
        c = r2 >> 9;
        f4 = r2 & 511;
        src = dir ? Whh_b : Whh_f;
        kloc = c * 32;
        dst = g_Wp1 + (size_t)id * 4;
    } else {
        int id2 = id - 2097152;                  // g_Wp2: [dir][nb][64][2048]
        if (id2 >= 4194304) return;
        int dir = id2 >> 21;
        int r = id2 & 2097151;
        nb = r >> 15;
        int r2 = r & 32767;
        c = r2 >> 9;
        f4 = r2 & 511;
        src = ((c < 32) ? (dir ? Wih_b : Wih_f) : (dir ? Whh_b : Whh_f)) + 4194304;
        kloc = (c & 31) * 32;
        dst = g_Wp2 + (size_t)id2 * 4;
    }
    int frag = f4 >> 4, rem = f4 & 15;
    int k8 = frag >> 3, wn = (frag >> 2) & 1, nt = frag & 3;
    float out[4];
    #pragma unroll
    for (int j = 0; j < 4; j++) {
        int lane = rem * 2 + (j >> 1);
        int pr = j & 1;
        int gq = lane >> 2, tig = lane & 3;
        int n = wn * 32 + nt * 8 + gq;
        int grow = (n >> 4) * 1024 + nb * 16 + (n & 15);
        int k = kloc + k8 * 8 + tig + 4 * pr;
        out[j] = __ldcs(&src[(size_t)grow * 1024 + k]);
    }
    *(float4*)dst = *(float4*)out;
}

// Precompute G0 = x @ Wih0^T (+ bias sums), both directions.
__global__ __launch_bounds__(256) void g0_kernel(
    const float* __restrict__ x,
    const float* __restrict__ Wih_f, const float* __restrict__ Wih_b)
{
    __shared__ float sA[2][64 * LDS];
    __shared__ float sW[2][64 * LDS];

    const int tid = threadIdx.x;
    const int bx = blockIdx.x;
    const int mtile = bx >> 7;
    const int ntile = bx & 127;
    const int dir = ntile >> 6;
    const bool revA = (dir == 1);
    const float* Ap = x + (size_t)mtile * 64 * HDIM;
    const float* Wp = dir ? Wih_b : Wih_f;
    const int wrowbase = (ntile & 63) * 64;

    const int rowA0 = tid >> 3, kq = tid & 7, rowA1 = rowA0 + 32;
    const int wr0 = wrowbase + rowA0;
    const int wr1 = wrowbase + rowA1;

    float4 ra0, ra1, rw0, rw1;
    auto do_load = [&](int kc) {
        int kl = kc * KC + kq * 4;
        if (!revA) {
            ra0 = *(const float4*)(Ap + (size_t)rowA0 * HDIM + kl);
            ra1 = *(const float4*)(Ap + (size_t)rowA1 * HDIM + kl);
        } else {
            ra0 = *(const float4*)(Ap + (size_t)rowA0 * HDIM + (HDIM - 4) - kl);
            ra1 = *(const float4*)(Ap + (size_t)rowA1 * HDIM + (HDIM - 4) - kl);
        }
        rw0 = *(const float4*)(Wp + (size_t)wr0 * HDIM + kl);
        rw1 = *(const float4*)(Wp + (size_t)wr1 * HDIM + kl);
    };
    auto rev4 = [](float4 v) { float4 r; r.x = v.w; r.y = v.z; r.z = v.y; r.w = v.x; return r; };
    auto do_store = [&](int buf) {
        float4 a0 = cvt4(ra0), a1 = cvt4(ra1);
        if (revA) { a0 = rev4(a0); a1 = rev4(a1); }
        *(float4*)(&sA[buf][rowA0 * LDS + kq * 4]) = a0;
        *(float4*)(&sA[buf][rowA1 * LDS + kq * 4]) = a1;
        *(float4*)(&sW[buf][rowA0 * LDS + kq * 4]) = cvt4(rw0);
        *(float4*)(&sW[buf][rowA1 * LDS + kq * 4]) = cvt4(rw1);
    };

    const int wid = tid >> 5, lane = tid & 31;
    const int wm = wid & 3, wn = wid >> 2;
    const int gq = lane >> 2, tig = lane & 3;

    float acc[4][4];
    #pragma unroll
    for (int i = 0; i < 4; i++)
        #pragma unroll
        for (int j = 0; j < 4; j++) acc[i][j] = 0.f;

    do_load(0);
    do_store(0);
    __syncthreads();

    for (int kc = 0; kc < 32; kc++) {
        int buf = kc & 1;
        if (kc + 1 < 32) do_load(kc + 1);
        const float* aB = &sA[buf][(wm * 16 + gq) * LDS];
        #pragma unroll
        for (int k8 = 0; k8 < 4; k8++) {
            int kk = k8 * 8;
            float af[4];
            af[0] = aB[kk + tig];
            af[1] = aB[8 * LDS + kk + tig];
            af[2] = aB[kk + tig + 4];
            af[3] = aB[8 * LDS + kk + tig + 4];
            #pragma unroll
            for (int nt = 0; nt < 4; nt++) {
                int nl = wn * 32 + nt * 8 + gq;
                mma8(acc[nt], af, sW[buf][nl * LDS + kk + tig], sW[buf][nl * LDS + kk + tig + 4]);
            }
        }
        if (kc + 1 < 32) do_store(buf ^ 1);
        __syncthreads();
    }

    // scatter D + bias directly to g_G0 ([T][dir][B][4096]), streaming stores
    int b = mtile >> 3, tb = (mtile & 7) * 64;
    int ncd = (ntile & 63) * 64 + wn * 32;
    int r0 = wm * 16 + gq;
    #pragma unroll
    for (int nt = 0; nt < 4; nt++) {
        int cc = ncd + nt * 8 + tig * 2;
        float bs0 = g_bsum[dir][cc], bs1 = g_bsum[dir][cc + 1];
        size_t d0 = ((size_t)((tb + r0) * 2 + dir) * 64 + b) * (size_t)G4 + cc;
        size_t d2 = ((size_t)((tb + r0 + 8) * 2 + dir) * 64 + b) * (size_t)G4 + cc;
        __stcs(&g_G0[d0], acc[nt][0] + bs0);
        __stcs(&g_G0[d0 + 1], acc[nt][1] + bs1);
        __stcs(&g_G0[d2], acc[nt][2] + bs0);
        __stcs(&g_G0[d2 + 1], acc[nt][3] + bs1);
    }
}

// merged bias-sum + state-zero init (single launch)
__global__ void init_kernel(const float* __restrict__ bih_f, const float* __restrict__ bhh_f,
                            const float* __restrict__ bih_b, const float* __restrict__ bhh_b) {
    int i = blockIdx.x * 256 + threadIdx.x;
    if (i < 4096) {
        g_bsum[0][i] = bih_f[i] + bhh_f[i];
        g_bsum[2][i] = bih_f[4096 + i] + bhh_f[4096 + i];
        g_bsum[1][i] = bih_b[i] + bhh_b[i];
        g_bsum[3][i] = bih_b[4096 + i] + bhh_b[4096 + i];
    }
    if (i < 2 * BSZ * HDIM) {
        (&g_h0[0][0])[i] = 0.f;
        (&g_c0[0][0])[i] = 0.f;
        (&g_h1[0][0])[i] = 0.f;
        (&g_c1[0][0])[i] = 0.f;
    }
}

extern "C" void kernel_launch(void* const* d_in, const int* in_sizes, int n_in,
                              void* d_out, int out_size) {
    const float* x     = (const float*)d_in[0];
    const float* Wih_f = (const float*)d_in[1];
    const float* Whh_f = (const float*)d_in[2];
    const float* bih_f = (const float*)d_in[3];
    const float* bhh_f = (const float*)d_in[4];
    const float* Wih_b = (const float*)d_in[5];
    const float* Whh_b = (const float*)d_in[6];
    const float* bih_b = (const float*)d_in[7];
    const float* bhh_b = (const float*)d_in[8];
    float* out = (float*)d_out;

    static bool attr_set = false;
    if (!attr_set) {
        cudaFuncSetAttribute(scan_kernel, cudaFuncAttributeMaxDynamicSharedMemorySize, SMEM_BYTES);
        attr_set = true;
    }

    init_kernel<<<512, 256>>>(bih_f, bhh_f, bih_b, bhh_b);
    pack_kernel<<<24576, 256>>>(Whh_f, Whh_b, Wih_f, Wih_b);
    g0_kernel<<<65536, 256>>>(x, Wih_f, Wih_b);
    scan_kernel<<<NBLK, NTHR, SMEM_BYTES>>>(out);
}

// round 14
// speedup vs baseline: 2.8351x; 1.1690x over previous
#include <cuda_runtime.h>
#include <cuda_fp16.h>
#include <cstdint>

#define HDIM 1024
#define BSZ 64
#define TLEN 512
#define G4 4096
#define KC 32
#define LDS 36
#define NBLK 128
#define NTHR 512
#define NGRP 4
#define STAGES 3
#define STG_A 2304               // 64 x 36 padded A stage (floats)
#define STG_W 2048               // fragment-ordered W stage (64x32 chunk, floats)
#define STGT (STG_A + STG_W)     // 4352 floats per stage
#define GSLAB 4160               // 64 x 65 partial slab per group (floats)
#define SMEM_FLOATS (NGRP * STAGES * STGT + 4096)
#define SMEM_BYTES (SMEM_FLOATS * 4)
// fp16 g0 kernel stage sizes (bytes)
#define HSTG_A 5120              // 64 rows x 80B (32 fp16 + 16B pad)
#define HSTG_W 4096              // fp16 fragment chunk
#define HSTGT (HSTG_A + HSTG_W)  // 9216
#define G0H_SMEM (NGRP * 3 * HSTGT)   // 110592

// scratch (device statics; no allocations)
__device__ float g_G0[268435456];          // [T][dir][B][4096] precomputed x-gates (+bias), 1 GiB
__device__ float g_Wp1[33554432];          // packed phase1 W fp32 frags [dir][nb][c:32][8KB]
__device__ float g_Wp2[67108864];          // packed phase2 W fp32 frags [dir][nb][c:64][8KB]
__device__ __align__(16) unsigned g_Wp0[4194304];   // packed g0 Wih fp16 frags [dir][nt:64][c:32][4KB]
__device__ __align__(16) __half g_xh[67108864];     // [orient 0=fwd,1=rev][32768][1024] fp16 x
__device__ float g_bsum[4][G4];            // bias sums: f0, b0, f1, b1
__device__ float g_h0[2][BSZ * HDIM];      // layer0 carried h (backward), ping-pong (tf32-rounded)
__device__ float g_c0[2][BSZ * HDIM];
__device__ float g_h1[2][BSZ * HDIM];      // layer1 carried h, ping-pong
__device__ float g_c1[2][BSZ * HDIM];
__device__ float g_hf0[2][BSZ * HDIM];     // layer0 forward h, ping-pong
__device__ unsigned g_gen;
__device__ unsigned g_cnt;

__device__ __forceinline__ float f2tf32(float x) {
    unsigned u;
    asm("cvt.rna.tf32.f32 %0, %1;" : "=r"(u) : "f"(x));
    return __uint_as_float(u);
}

// tf32 mma (scan)
__device__ __forceinline__ void mma8(float acc[4], const float a[4], const float b0, const float b1) {
    const unsigned* A = reinterpret_cast<const unsigned*>(a);
    asm volatile(
        "mma.sync.aligned.m16n8k8.row.col.f32.tf32.tf32.f32 "
        "{%0,%1,%2,%3}, {%4,%5,%6,%7}, {%8,%9}, {%0,%1,%2,%3};\n"
        : "+f"(acc[0]), "+f"(acc[1]), "+f"(acc[2]), "+f"(acc[3])
        : "r"(A[0]), "r"(A[1]), "r"(A[2]), "r"(A[3]),
          "r"(__float_as_uint(b0)), "r"(__float_as_uint(b1)));
}

// fp32-accumulate fp16 mma (g0)
__device__ __forceinline__ void mma16(float acc[4], unsigned a0, unsigned a1,
                                      unsigned a2, unsigned a3, unsigned b0, unsigned b1) {
    asm volatile(
        "mma.sync.aligned.m16n8k16.row.col.f32.f16.f16.f32 "
        "{%0,%1,%2,%3}, {%4,%5,%6,%7}, {%8,%9}, {%0,%1,%2,%3};\n"
        : "+f"(acc[0]), "+f"(acc[1]), "+f"(acc[2]), "+f"(acc[3])
        : "r"(a0), "r"(a1), "r"(a2), "r"(a3), "r"(b0), "r"(b1));
}

// fast, overflow-safe activations
__device__ __forceinline__ float sigf(float x) {
    return __fdividef(1.0f, 1.0f + __expf(-x));
}
__device__ __forceinline__ float tanh_(float x) {
    float a = fabsf(x);
    float e = __expf(-2.0f * a);
    float r = __fdividef(1.0f - e, 1.0f + e);
    return copysignf(r, x);
}

__device__ __forceinline__ uint64_t mkpol_last() {
    uint64_t p;
    asm("createpolicy.fractional.L2::evict_last.b64 %0, 1.0;" : "=l"(p));
    return p;
}
__device__ __forceinline__ uint64_t mkpol_first() {
    uint64_t p;
    asm("createpolicy.fractional.L2::evict_first.b64 %0, 1.0;" : "=l"(p));
    return p;
}
__device__ __forceinline__ void cp16(void* dst, const void* src) {
    unsigned d = (unsigned)__cvta_generic_to_shared(dst);
    asm volatile("cp.async.cg.shared.global [%0], [%1], 16;" :: "r"(d), "l"(src));
}
__device__ __forceinline__ void cp16p(void* dst, const void* src, uint64_t pol) {
    unsigned d = (unsigned)__cvta_generic_to_shared(dst);
    asm volatile("cp.async.cg.shared.global.L2::cache_hint [%0], [%1], 16, %2;"
                 :: "r"(d), "l"(src), "l"(pol));
}
#define CP_COMMIT() asm volatile("cp.async.commit_group;")
#define CP_WAIT(n)  asm volatile("cp.async.wait_group %0;" :: "n"(n))

// per-K-group barrier (128 threads each, barrier ids 1..4)
__device__ __forceinline__ void group_bar(int kw) {
    asm volatile("bar.sync %0, 128;" :: "r"(kw + 1) : "memory");
}

// Software grid barrier. 128 blocks <= 148 SMs (co-resident). Acquire/release
// on the flag only — all cross-block data reads bypass L1 (cp.async.cg/__ldcg).
__device__ __forceinline__ void grid_bar() {
    __syncthreads();
    if (threadIdx.x == 0) {
        unsigned gen;
        asm volatile("ld.acquire.gpu.global.u32 %0, [%1];" : "=r"(gen) : "l"(&g_gen));
        unsigned arrived;
        asm volatile("atom.release.gpu.global.add.u32 %0, [%1], 1;"
                     : "=r"(arrived) : "l"(&g_cnt));
        if (arrived == NBLK - 1) {
            g_cnt = 0;
            asm volatile("st.release.gpu.global.u32 [%0], %1;" :: "l"(&g_gen), "r"(gen + 1));
        } else {
            unsigned cur;
            do {
                __nanosleep(20);
                asm volatile("ld.acquire.gpu.global.u32 %0, [%1];" : "=r"(cur) : "l"(&g_gen));
            } while (cur == gen);
        }
    }
    __syncthreads();
}

// ---------------------------------------------------------------------------
// One tf32-GEMM + LSTM phase, K-split across FOUR 4-warp groups (32x32 tiles).
// mode 1: layer0  gates = G0[t] + h_prev0 @ Whh0^T           (32 chunks: 8/group)
// mode 2: layer1  gates = h_in @ Wih1^T + h_prev1 @ Whh1^T   (64 chunks: 16/group)
// ---------------------------------------------------------------------------
__device__ __forceinline__ void scan_phase(
    int mode, int t, int dir, int nblk,
    float* __restrict__ dout,
    float* smem, float* sG,
    uint64_t polL, uint64_t polF)
{
    const int tid = threadIdx.x;
    const int kw = tid >> 7;                  // K-group 0..3
    const int ltid = tid & 127;
    const int p = t & 1;
    const int n0 = nblk * 16;

    const float *Ag, *Wb;
    int nh;
    if (mode == 1) {
        Ag = g_h0[p];
        Wb = g_Wp1 + (size_t)(dir * 64 + nblk) * 32 * 2048;
        nh = 8;
    } else {
        Ag = (kw < 2) ? (dir ? g_h0[1 - p] : g_hf0[1 - p]) : g_h1[p];
        Wb = g_Wp2 + (size_t)(dir * 64 + nblk) * 64 * 2048;
        nh = 16;
    }

    float* sBase = smem + kw * (STAGES * STGT);

    auto prefetch_g0 = [&](int tt) {
        int mRow = tid >> 3, seg = (tid >> 1) & 3, half = tid & 1;
        const float* src = g_G0 + ((size_t)(2 * tt + dir) * 64 + mRow) * (size_t)G4
                         + seg * HDIM + n0 + half * 8;
        float* dst = sG + mRow * 64 + seg * 16 + half * 8;
        cp16p(dst, src, polF); cp16p(dst + 4, src + 4, polF);
    };

    auto issue = [&](int c, int buf) {
        if (c < nh) {
            int gc = kw * nh + c;                       // global chunk
            int klA = ((mode == 1) ? gc : (gc & 31)) * KC;
            float* dA = sBase + buf * STGT;
            float* dW = dA + STG_A;
            const float* wsrc = Wb + (size_t)gc * 2048;
            #pragma unroll
            for (int i = 0; i < 4; i++) {
                int f = ltid + 128 * i;
                int row = f >> 3, kq = f & 7;
                cp16(dA + row * LDS + kq * 4, Ag + (size_t)row * HDIM + klA + kq * 4);
            }
            #pragma unroll
            for (int i = 0; i < 4; i++) {
                int f4 = ltid + 128 * i;
                cp16p(dW + f4 * 4, wsrc + (size_t)f4 * 4, polL);
            }
        }
        // inject next step's G0 prefetch mid-phase2 (fully hidden)
        if (mode == 2 && c == 8 && t + 1 < TLEN) prefetch_g0(t + 1);
        CP_COMMIT();
    };

    const int wid4 = (tid >> 5) & 3, lane = tid & 31;
    const int wm = wid4 >> 1, wn = wid4 & 1;    // warp tile: 32 rows x 32 cols
    const int gq = lane >> 2, tig = lane & 3;

    float acc[2][4][4];
    #pragma unroll
    for (int mt = 0; mt < 2; mt++)
        #pragma unroll
        for (int i = 0; i < 4; i++)
            #pragma unroll
            for (int j = 0; j < 4; j++) acc[mt][i][j] = 0.f;

    issue(0, 0);
    issue(1, 1);

    int buf = 0, nb = 2;
    for (int c = 0; c < nh; c++) {
        CP_WAIT(1);
        group_bar(kw);
        issue(c + 2, nb);
        const float* aB = sBase + buf * STGT + (wm * 32 + gq) * LDS;
        const float2* wF = (const float2*)(sBase + buf * STGT + STG_A);
        #pragma unroll
        for (int k8 = 0; k8 < 4; k8++) {
            int kk = k8 * 8;
            float af0[4], af1[4];
            af0[0] = aB[kk + tig];
            af0[1] = aB[8 * LDS + kk + tig];
            af0[2] = aB[kk + tig + 4];
            af0[3] = aB[8 * LDS + kk + tig + 4];
            af1[0] = aB[16 * LDS + kk + tig];
            af1[1] = aB[24 * LDS + kk + tig];
            af1[2] = aB[16 * LDS + kk + tig + 4];
            af1[3] = aB[24 * LDS + kk + tig + 4];
            #pragma unroll
            for (int nt = 0; nt < 4; nt++) {
                float2 bv = wF[((k8 * 2 + wn) * 4 + nt) * 32 + lane];
                mma8(acc[0][nt], af0, bv.x, bv.y);
                mma8(acc[1][nt], af1, bv.x, bv.y);
            }
        }
        buf++; if (buf == STAGES) buf = 0;
        nb++;  if (nb == STAGES) nb = 0;
    }
    CP_WAIT(0);
    __syncthreads();

    // each group writes its partials to its own 64x65 slab
    {
        float* gsm = smem + kw * GSLAB;
        #pragma unroll
        for (int mt = 0; mt < 2; mt++) {
            int r0 = wm * 32 + mt * 16 + gq;
            #pragma unroll
            for (int nt = 0; nt < 4; nt++) {
                int cc = wn * 32 + nt * 8 + tig * 2;
                gsm[r0 * 65 + cc] = acc[mt][nt][0];
                gsm[r0 * 65 + cc + 1] = acc[mt][nt][1];
                gsm[(r0 + 8) * 65 + cc] = acc[mt][nt][2];
                gsm[(r0 + 8) * 65 + cc + 1] = acc[mt][nt][3];
            }
        }
    }
    __syncthreads();

    #pragma unroll
    for (int r = 0; r < 2; r++) {
        int idx = tid + NTHR * r;
        int m = idx >> 4, j = idx & 15;
        int base = m * 65 + j;
        float gi = 0.f, gf = 0.f, gg = 0.f, go = 0.f;
        #pragma unroll
        for (int g = 0; g < NGRP; g++) {
            const float* gs = smem + g * GSLAB;
            gi += gs[base];
            gf += gs[base + 16];
            gg += gs[base + 32];
            go += gs[base + 48];
        }
        int n = n0 + j;
        int hi = m * HDIM + n;
        if (mode == 1) {
            gi += sG[m * 64 + j];
            gf += sG[m * 64 + 16 + j];
            gg += sG[m * 64 + 32 + j];
            go += sG[m * 64 + 48 + j];
            float cp = __ldcg(&g_c0[p][hi]);
            float c2 = sigf(gf) * cp + sigf(gi) * tanh_(gg);
            float h2 = sigf(go) * tanh_(c2);
            if (dir == 0) {
                g_hf0[1 - p][hi] = f2tf32(h2);
            } else {
                g_h0[1 - p][hi] = f2tf32(h2);
                g_c0[1 - p][hi] = c2;
            }
        } else {
            gi += g_bsum[2 + dir][n];
            gf += g_bsum[2 + dir][HDIM + n];
            gg += g_bsum[2 + dir][2 * HDIM + n];
            go += g_bsum[2 + dir][3 * HDIM + n];
            float cp = __ldcg(&g_c1[p][hi]);
            float c2 = sigf(gf) * cp + sigf(gi) * tanh_(gg);
            float h2 = sigf(go) * tanh_(c2);
            size_t ob = ((size_t)m * TLEN + t) * 2048 + (size_t)dir * HDIM + n;
            __stcs(&dout[ob], h2);                           // out
            __stcs(&dout[67108864 + ob], c2);                // c_out
            if (t == TLEN - 1) {
                size_t lb = (size_t)m * 2048 + (size_t)dir * HDIM + n;
                dout[134217728 + lb] = h2;                   // out[:, -1]
                dout[134217728 + 131072 + lb] = c2;          // c_out[:, -1]
            }
            if (dir == 1) {
                g_h1[1 - p][hi] = f2tf32(h2);
                g_c1[1 - p][hi] = c2;
            }
        }
    }
    __syncthreads();   // protect smem before next phase's prologue
}

// Persistent scan kernel: entire 512-step recurrence in ONE launch.
__global__ __launch_bounds__(NTHR, 1) void scan_kernel(float* __restrict__ dout)
{
    extern __shared__ char dynsm[];
    float* smem = (float*)dynsm;
    float* sG = smem + NGRP * STAGES * STGT;

    const int bx = blockIdx.x;
    const int dir = bx >> 6;
    const int nblk = bx & 63;
    const int n0 = nblk * 16;
    const uint64_t polL = mkpol_last();
    const uint64_t polF = mkpol_first();

    // G0(t=0) prefetch (own group; drained by phase1(0)'s waits)
    {
        int tid = threadIdx.x;
        int mRow = tid >> 3, seg = (tid >> 1) & 3, half = tid & 1;
        const float* src = g_G0 + ((size_t)(0 + dir) * 64 + mRow) * (size_t)G4
                         + seg * HDIM + n0 + half * 8;
        float* dst = sG + mRow * 64 + seg * 16 + half * 8;
        cp16p(dst, src, polF); cp16p(dst + 4, src + 4, polF);
        CP_COMMIT();
    }

    for (int t = 0; t < TLEN; t++) {
        scan_phase(1, t, dir, nblk, dout, smem, sG, polL, polF);
        grid_bar();
        scan_phase(2, t, dir, nblk, dout, smem, sG, polL, polF);
        // phase1(t+1) touches only parity buffers in-flight phase2(t) never
        // reads; the t+1 barrier fences everything else.
    }
}

// Convert x to fp16, both forward and feature-reversed orientations.
__global__ void xconv_kernel(const float* __restrict__ x) {
    unsigned i = blockIdx.x * 256 + threadIdx.x;       // 8388608 float4 slots
    size_t r = i >> 8;
    int c4 = (int)(i & 255) * 4;
    float4 v = __ldcs((const float4*)(x + r * 1024 + c4));
    __half2 h01 = __floats2half2_rn(v.x, v.y);
    __half2 h23 = __floats2half2_rn(v.z, v.w);
    uint2 fw;
    fw.x = *(unsigned*)&h01;
    fw.y = *(unsigned*)&h23;
    *(uint2*)(g_xh + r * 1024 + c4) = fw;
    __half2 r01 = __lowhigh2highlow(h23);              // {w, z}
    __half2 r23 = __lowhigh2highlow(h01);              // {y, x}
    uint2 rv;
    rv.x = *(unsigned*)&r01;
    rv.y = *(unsigned*)&r23;
    *(uint2*)(g_xh + 33554432 + r * 1024 + (1020 - c4)) = rv;
}

// Repack weights:
//  seg A: g_Wp1 fp32 fragment order (scan phase1 Whh0)
//  seg B: g_Wp2 fp32 fragment order (scan phase2 Wih1|Whh1)
//  seg C: g_Wp0 fp16 fragment order (g0 Wih0, plain 64-row tiles)
__global__ void pack_kernel(
    const float* __restrict__ Whh_f, const float* __restrict__ Whh_b,
    const float* __restrict__ Wih_f, const float* __restrict__ Wih_b)
{
    int id = blockIdx.x * 256 + threadIdx.x;
    if (id < 6291456) {                          // fp32 segments (one float4 each)
        const float* src;
        float* dst;
        int nb, c, f4, kloc;
        if (id < 2097152) {                      // g_Wp1
            int dir = id >> 20;
            int r = id & 1048575;
            nb = r >> 14;
            int r2 = r & 16383;
            c = r2 >> 9;
            f4 = r2 & 511;
            src = dir ? Whh_b : Whh_f;
            kloc = c * 32;
            dst = g_Wp1 + (size_t)id * 4;
        } else {
            int id2 = id - 2097152;              // g_Wp2
            int dir = id2 >> 21;
            int r = id2 & 2097151;
            nb = r >> 15;
            int r2 = r & 32767;
            c = r2 >> 9;
            f4 = r2 & 511;
            src = ((c < 32) ? (dir ? Wih_b : Wih_f) : (dir ? Whh_b : Whh_f)) + 4194304;
            kloc = (c & 31) * 32;
            dst = g_Wp2 + (size_t)id2 * 4;
        }
        int frag = f4 >> 4, rem = f4 & 15;
        int k8 = frag >> 3, wn = (frag >> 2) & 1, nt = frag & 3;
        float out[4];
        #pragma unroll
        for (int j = 0; j < 4; j++) {
            int lane = rem * 2 + (j >> 1);
            int pr = j & 1;
            int gq = lane >> 2, tig = lane & 3;
            int n = wn * 32 + nt * 8 + gq;
            int grow = (n >> 4) * 1024 + nb * 16 + (n & 15);
            int k = kloc + k8 * 8 + tig + 4 * pr;
            out[j] = __ldcs(&src[(size_t)grow * 1024 + k]);
        }
        *(float4*)dst = *(float4*)out;
    } else {                                     // seg C: g_Wp0 fp16 (one uint2 each)
        int id3 = id - 6291456;
        if (id3 >= 2097152) return;
        int dir = id3 >> 20;
        int r = id3 & 1048575;
        int ntl = r >> 14;                       // 0..63
        int r2 = r & 16383;
        int chunk = r2 >> 9;                     // 0..31
        int r3 = r2 & 511;
        int frag = r3 >> 5, lane = r3 & 31;
        int s = frag >> 3, wn = (frag >> 2) & 1, ntf = frag & 3;
        int gq = lane >> 2, tig = lane & 3;
        int n = wn * 32 + ntf * 8 + gq;
        int grow = ntl * 64 + n;
        int k0 = chunk * 32 + s * 16 + 2 * tig;
        const float* src = dir ? Wih_b : Wih_f;  // layer 0
        const float* ps = src + (size_t)grow * 1024 + k0;
        __half2 h01 = __floats2half2_rn(__ldcs(ps), __ldcs(ps + 1));
        __half2 h89 = __floats2half2_rn(__ldcs(ps + 8), __ldcs(ps + 9));
        uint2 v;
        v.x = *(unsigned*)&h01;
        v.y = *(unsigned*)&h89;
        *(((uint2*)g_Wp0) + id3) = v;
    }
}

// Precompute G0 = x @ Wih0^T (+ bias sums) with fp16 mma.
// Block = 64m x 64n x K1024, 512 threads, 4 K-groups of 4 warps (32x32 tiles).
__global__ __launch_bounds__(512, 1) void g0h_kernel()
{
    extern __shared__ char dynsm[];
    char* hsm = dynsm;
    const int tid = threadIdx.x, bx = blockIdx.x;
    const int mtile = bx >> 7;
    const int nt128 = bx & 127;
    const int dir = nt128 >> 6;
    const int ntl = nt128 & 63;
    const int kw = tid >> 7;
    const int ltid = tid & 127;

    const __half* Ag = g_xh + ((size_t)dir * 32768 + (size_t)mtile * 64) * 1024;
    const char* Wb = (const char*)g_Wp0 + (size_t)(dir * 64 + ntl) * 32 * 4096;
    char* sBase = hsm + kw * (3 * HSTGT);

    auto issue = [&](int c, int buf) {
        if (c < 8) {
            int gc = kw * 8 + c;
            int klA = gc * 32;                   // halfs
            char* dA = sBase + buf * HSTGT;
            char* dW = dA + HSTG_A;
            const char* wsrc = Wb + (size_t)gc * 4096;
            #pragma unroll
            for (int i = 0; i < 2; i++) {
                int f = ltid + 128 * i;
                int row = f >> 2, kq = f & 3;
                cp16(dA + row * 80 + kq * 16, Ag + (size_t)row * 1024 + klA + kq * 8);
            }
            #pragma unroll
            for (int i = 0; i < 2; i++) {
                int f4 = ltid + 128 * i;
                cp16(dW + f4 * 16, wsrc + (size_t)f4 * 16);
            }
        }
        CP_COMMIT();
    };

    const int wid4 = (tid >> 5) & 3, lane = tid & 31;
    const int wm = wid4 >> 1, wn = wid4 & 1;
    const int gq = lane >> 2, tig = lane & 3;

    float acc[2][4][4];
    #pragma unroll
    for (int mt = 0; mt < 2; mt++)
        #pragma unroll
        for (int i = 0; i < 4; i++)
            #pragma unroll
            for (int j = 0; j < 4; j++) acc[mt][i][j] = 0.f;

    issue(0, 0);
    issue(1, 1);

    int buf = 0, nb = 2;
    for (int c = 0; c < 8; c++) {
        CP_WAIT(1);
        group_bar(kw);
        issue(c + 2, nb);
        const unsigned* aU = (const unsigned*)(sBase + buf * HSTGT);
        const uint2* wF = (const uint2*)(sBase + buf * HSTGT + HSTG_A);
        #pragma unroll
        for (int s = 0; s < 2; s++) {
            unsigned a0[2], a1[2], a2[2], a3[2];
            #pragma unroll
            for (int mt = 0; mt < 2; mt++) {
                int base = (wm * 32 + mt * 16 + gq) * 20 + s * 8 + tig;
                a0[mt] = aU[base];
                a1[mt] = aU[base + 160];         // +8 rows
                a2[mt] = aU[base + 4];           // k+8
                a3[mt] = aU[base + 164];
            }
            #pragma unroll
            for (int nt = 0; nt < 4; nt++) {
                uint2 bv = wF[((s * 2 + wn) * 4 + nt) * 32 + lane];
                mma16(acc[0][nt], a0[0], a1[0], a2[0], a3[0], bv.x, bv.y);
                mma16(acc[1][nt], a0[1], a1[1], a2[1], a3[1], bv.x, bv.y);
            }
        }
        buf++; if (buf == 3) buf = 0;
        nb++;  if (nb == 3) nb = 0;
    }
    CP_WAIT(0);
    __syncthreads();

    // per-group slabs
    {
        float* gsm = (float*)(hsm + kw * (GSLAB * 4));
        #pragma unroll
        for (int mt = 0; mt < 2; mt++) {
            int r0 = wm * 32 + mt * 16 + gq;
            #pragma unroll
            for (int nt = 0; nt < 4; nt++) {
                int cc = wn * 32 + nt * 8 + tig * 2;
                gsm[r0 * 65 + cc] = acc[mt][nt][0];
                gsm[r0 * 65 + cc + 1] = acc[mt][nt][1];
                gsm[(r0 + 8) * 65 + cc] = acc[mt][nt][2];
                gsm[(r0 + 8) * 65 + cc + 1] = acc[mt][nt][3];
            }
        }
    }
    __syncthreads();

    // combine 4 slabs + bias, scatter to g_G0 [T][dir][B][4096]
    int b = mtile >> 3, tb = (mtile & 7) * 64;
    #pragma unroll
    for (int r = 0; r < 8; r++) {
        int idx = tid + 512 * r;
        int m = idx >> 6, cc = idx & 63;
        float s = 0.f;
        #pragma unroll
        for (int g = 0; g < NGRP; g++)
            s += ((const float*)(hsm + g * (GSLAB * 4)))[m * 65 + cc];
        int col = ntl * 64 + cc;
        s += g_bsum[dir][col];
        size_t d = ((size_t)((tb + m) * 2 + dir) * 64 + b) * (size_t)G4 + col;
        __stcs(&g_G0[d], s);
    }
}

// merged bias-sum + state-zero init (single launch)
__global__ void init_kernel(const float* __restrict__ bih_f, const float* __restrict__ bhh_f,
                            const float* __restrict__ bih_b, const float* __restrict__ bhh_b) {
    int i = blockIdx.x * 256 + threadIdx.x;
    if (i < 4096) {
        g_bsum[0][i] = bih_f[i] + bhh_f[i];
        g_bsum[2][i] = bih_f[4096 + i] + bhh_f[4096 + i];
        g_bsum[1][i] = bih_b[i] + bhh_b[i];
        g_bsum[3][i] = bih_b[4096 + i] + bhh_b[4096 + i];
    }
    if (i < 2 * BSZ * HDIM) {
        (&g_h0[0][0])[i] = 0.f;
        (&g_c0[0][0])[i] = 0.f;
        (&g_h1[0][0])[i] = 0.f;
        (&g_c1[0][0])[i] = 0.f;
    }
}

extern "C" void kernel_launch(void* const* d_in, const int* in_sizes, int n_in,
                              void* d_out, int out_size) {
    const float* x     = (const float*)d_in[0];
    const float* Wih_f = (const float*)d_in[1];
    const float* Whh_f = (const float*)d_in[2];
    const float* bih_f = (const float*)d_in[3];
    const float* bhh_f = (const float*)d_in[4];
    const float* Wih_b = (const float*)d_in[5];
    const float* Whh_b = (const float*)d_in[6];
    const float* bih_b = (const float*)d_in[7];
    const float* bhh_b = (const float*)d_in[8];
    float* out = (float*)d_out;

    static bool attr_set = false;
    if (!attr_set) {
        cudaFuncSetAttribute(scan_kernel, cudaFuncAttributeMaxDynamicSharedMemorySize, SMEM_BYTES);
        cudaFuncSetAttribute(g0h_kernel, cudaFuncAttributeMaxDynamicSharedMemorySize, G0H_SMEM);
        attr_set = true;
    }

    init_kernel<<<512, 256>>>(bih_f, bhh_f, bih_b, bhh_b);
    xconv_kernel<<<32768, 256>>>(x);
    pack_kernel<<<32768, 256>>>(Whh_f, Whh_b, Wih_f, Wih_b);
    g0h_kernel<<<65536, 512, G0H_SMEM>>>();
    scan_kernel<<<NBLK, NTHR, SMEM_BYTES>>>(out);
}